// round 6
// baseline (speedup 1.0000x reference)
#include <cuda_runtime.h>
#include <cuda_fp16.h>
#include <cuda_bf16.h>

// Problem constants
#define BB 8
#define CC 32
#define TT 12
#define NNODE 5000
#define EDGES 80000
#define FF (BB*TT*CC)       // 3072 features per node
#define BT (BB*TT)          // 96
#define EPAD (EDGES + NNODE*7 + 8)  // padded CSR capacity

// ---------------------------------------------------------------------------
// Scratch (static __device__ arrays — no allocations allowed)
// ---------------------------------------------------------------------------
__device__ __align__(16) __half g_y  [(size_t)(NNODE + 1) * FF]; // +1 dummy zero node
__device__ __align__(16) __half g_agg[(size_t)NNODE * FF];
__device__ int    g_ptr    [NNODE + 1];        // padded CSR row ptr by dst
__device__ int    g_csr_src[EPAD];             // src per edge (padded w/ NNODE)
__device__ float  g_norm_src[NNODE];
__device__ float  g_norm_dst[NNODE];

// ---------------------------------------------------------------------------
// K_prep: one block, 40KB static smem (<48KB limit — R4 had 60KB and failed
// to compile). Degree histograms (smem atomics), norms, warp-shuffle
// exclusive scan of degrees padded to multiples of 8 (ptr written back into
// s_in in place; true degree kept in registers), CSR scatter, pad fill,
// zeroing of the dummy node's y row.
// ---------------------------------------------------------------------------
__global__ __launch_bounds__(1024, 1)
void k_prep(const int* __restrict__ src, const int* __restrict__ dst) {
    __shared__ int s_in [NNODE];   // deg_in histogram -> padded exclusive ptr
    __shared__ int s_out[NNODE];   // deg_out -> scatter cursor
    __shared__ int s_wsum[32];

    const int tid  = threadIdx.x;
    const int lane = tid & 31;
    const int warp = tid >> 5;

    for (int i = tid; i < NNODE; i += 1024) { s_in[i] = 0; s_out[i] = 0; }
    __syncthreads();

    for (int e = tid; e < EDGES; e += 1024) {
        atomicAdd(&s_out[src[e]], 1);
        atomicAdd(&s_in [dst[e]], 1);
    }
    __syncthreads();

    // norms (true degrees); reads complete before any __syncthreads below
    for (int i = tid; i < NNODE; i += 1024) {
        g_norm_src[i] = rsqrtf((float)max(s_out[i], 1));
        g_norm_dst[i] = rsqrtf((float)max(s_in [i], 1));
    }

    // scan of PADDED degrees (5 elems/thread); true degrees -> registers
    const int base = tid * 5;
    int deg[5], pdeg[5];
    int tsum = 0;
    #pragma unroll
    for (int k = 0; k < 5; k++) {
        deg[k]  = (base + k < NNODE) ? s_in[base + k] : 0;
        pdeg[k] = (deg[k] + 7) & ~7;
        tsum += pdeg[k];
    }
    int incl = tsum;
    #pragma unroll
    for (int off = 1; off < 32; off <<= 1) {
        int t = __shfl_up_sync(0xffffffffu, incl, off);
        if (lane >= off) incl += t;
    }
    if (lane == 31) s_wsum[warp] = incl;
    __syncthreads();                      // also fences norm/scan reads of s_in
    if (warp == 0) {
        int w = s_wsum[lane];
        int wi = w;
        #pragma unroll
        for (int off = 1; off < 32; off <<= 1) {
            int t = __shfl_up_sync(0xffffffffu, wi, off);
            if (lane >= off) wi += t;
        }
        s_wsum[lane] = wi - w;            // exclusive warp offsets
    }
    __syncthreads();

    // write padded exclusive ptr IN PLACE into s_in; fill padding slots
    int run = s_wsum[warp] + incl - tsum; // exclusive prefix at base
    #pragma unroll
    for (int k = 0; k < 5; k++) {
        int idx = base + k;
        if (idx < NNODE) {
            g_ptr[idx] = run;
            s_in [idx] = run;
            for (int j = deg[k]; j < pdeg[k]; j++) g_csr_src[run + j] = NNODE;
            run += pdeg[k];
        }
    }
    if (tid == (NNODE + 4) / 5 - 1) g_ptr[NNODE] = run;   // grand total

    // reset cursor (same thread zeroes the s_out[i] it norm-read — no race)
    for (int i = tid; i < NNODE; i += 1024) s_out[i] = 0;
    __syncthreads();

    // scatter edges by dst (pad slots are disjoint from these positions)
    for (int e = tid; e < EDGES; e += 1024) {
        int d = dst[e];
        int pos = s_in[d] + atomicAdd(&s_out[d], 1);
        g_csr_src[pos] = src[e];
    }

    // zero dummy node's y row (FF halves = FF/8 uint4)
    uint4 z = make_uint4(0, 0, 0, 0);
    uint4* dy = reinterpret_cast<uint4*>(g_y + (size_t)NNODE * FF);
    for (int i = tid; i < FF / 8; i += 1024) dy[i] = z;
}

// ---------------------------------------------------------------------------
// K_y: y[n][bt][c'] = norm_src[n] * sum_c x[b,c,t,n] * W[c][c']  (fp16 out)
// x loads coalesced over n; y stored node-major via uint4 (8 halves).
// ---------------------------------------------------------------------------
__global__ void k_y(const float* __restrict__ x, const float* __restrict__ W) {
    __shared__ float Ws[CC * CC];
    int tid = threadIdx.y * 32 + threadIdx.x;
    for (int i = tid; i < CC * CC; i += 256) Ws[i] = W[i];
    __syncthreads();

    int n  = blockIdx.x * 32 + threadIdx.x;
    int bt = blockIdx.y * 8 + threadIdx.y;
    if (n >= NNODE) return;
    int b = bt / TT, t = bt - b * TT;

    const float* xp = x + ((size_t)b * CC * TT) * NNODE + (size_t)t * NNODE + n;
    float xa[CC];
    #pragma unroll
    for (int c = 0; c < CC; c++) xa[c] = xp[(size_t)c * TT * NNODE];

    float ns = g_norm_src[n];
    uint4* yp = reinterpret_cast<uint4*>(g_y + (size_t)n * FF + (size_t)bt * CC);
    #pragma unroll
    for (int c8 = 0; c8 < CC / 8; c8++) {
        float acc[8];
        #pragma unroll
        for (int j = 0; j < 8; j++) acc[j] = 0.f;
        #pragma unroll
        for (int c = 0; c < CC; c++) {
            float xv = xa[c];
            const float* wr = &Ws[c * CC + c8 * 8];
            #pragma unroll
            for (int j = 0; j < 8; j++) acc[j] += xv * wr[j];
        }
        __half2 h[4];
        #pragma unroll
        for (int j = 0; j < 4; j++)
            h[j] = __floats2half2_rn(acc[2*j] * ns, acc[2*j+1] * ns);
        uint4 pack;
        pack.x = *reinterpret_cast<unsigned*>(&h[0]);
        pack.y = *reinterpret_cast<unsigned*>(&h[1]);
        pack.z = *reinterpret_cast<unsigned*>(&h[2]);
        pack.w = *reinterpret_cast<unsigned*>(&h[3]);
        yp[c8] = pack;
    }
}

// ---------------------------------------------------------------------------
// K_agg: agg[d] = norm_dst[d] * sum_{e in CSR[d]} y[src[e]]
// One block per dst node, 384 threads, 1 uint4 (8 halves) per thread.
// Per group of 8 edges: fp16 HADD2 accumulation (full-rate, no F2F cvts),
// then one upconvert into fp32 accumulators. Padding edges hit the zeroed
// dummy node row -> branch-free inner loop, 8 independent LDG.128 in flight.
// ---------------------------------------------------------------------------
__global__ __launch_bounds__(384)
void k_agg() {
    int d = blockIdx.x;
    int tid = threadIdx.x;
    int beg = g_ptr[d], end = g_ptr[d + 1];   // multiple of 8 edges

    float2 acc[4];
    #pragma unroll
    for (int j = 0; j < 4; j++) acc[j] = make_float2(0.f, 0.f);

    __shared__ int ss[128];
    for (int base = beg; base < end; base += 128) {
        int m = min(128, end - base);          // multiple of 8
        if (tid < m) ss[tid] = g_csr_src[base + tid];
        __syncthreads();
        for (int g0 = 0; g0 < m; g0 += 8) {
            __half2 h[4];
            #pragma unroll
            for (int j = 0; j < 4; j++) h[j] = __floats2half2_rn(0.f, 0.f);
            #pragma unroll
            for (int k = 0; k < 8; k++) {
                const uint4* ys =
                    reinterpret_cast<const uint4*>(g_y + (size_t)ss[g0 + k] * FF);
                uint4 v = ys[tid];
                h[0] = __hadd2(h[0], *reinterpret_cast<const __half2*>(&v.x));
                h[1] = __hadd2(h[1], *reinterpret_cast<const __half2*>(&v.y));
                h[2] = __hadd2(h[2], *reinterpret_cast<const __half2*>(&v.z));
                h[3] = __hadd2(h[3], *reinterpret_cast<const __half2*>(&v.w));
            }
            #pragma unroll
            for (int j = 0; j < 4; j++) {
                float2 f = __half22float2(h[j]);
                acc[j].x += f.x; acc[j].y += f.y;
            }
        }
        __syncthreads();
    }

    float nd = g_norm_dst[d];
    __half2 o[4];
    #pragma unroll
    for (int j = 0; j < 4; j++)
        o[j] = __floats2half2_rn(acc[j].x * nd, acc[j].y * nd);
    uint4 pack;
    pack.x = *reinterpret_cast<unsigned*>(&o[0]);
    pack.y = *reinterpret_cast<unsigned*>(&o[1]);
    pack.z = *reinterpret_cast<unsigned*>(&o[2]);
    pack.w = *reinterpret_cast<unsigned*>(&o[3]);
    reinterpret_cast<uint4*>(g_agg + (size_t)d * FF)[tid] = pack;
}

// ---------------------------------------------------------------------------
// K_out: out[b,c,t,n] = relu(x[b,c,t,n] + bias[c] + agg[n][b][t][c])
// 128-node tiles, float4 LDG/STG for x/out; agg staged via smem transpose.
// ---------------------------------------------------------------------------
__global__ __launch_bounds__(256)
void k_out(const float* __restrict__ x, const float* __restrict__ bias,
           float* __restrict__ out) {
    __shared__ float s[CC][132];   // [c][n], row stride 132
    int bt = blockIdx.y;
    int b = bt / TT, t = bt - b * TT;
    int n0 = blockIdx.x * 128;
    int tid = threadIdx.y * 32 + threadIdx.x;

    // Stage agg[n0..n0+127][bt*32..+32) -> s[c][nl]. Each node row = 4 uint4.
    {
        int nl   = tid >> 1;           // 0..127
        int part = tid & 1;            // halves of the 32-c row
        int n = n0 + nl;
        if (n < NNODE) {
            const uint4* ar =
                reinterpret_cast<const uint4*>(g_agg + (size_t)n * FF + (size_t)bt * CC);
            #pragma unroll
            for (int q = 0; q < 2; q++) {
                uint4 v = ar[part * 2 + q];
                int c0 = part * 16 + q * 8;
                const unsigned* u = &v.x;
                #pragma unroll
                for (int j = 0; j < 4; j++) {
                    float2 f = __half22float2(*reinterpret_cast<const __half2*>(&u[j]));
                    s[c0 + 2*j    ][nl] = f.x;
                    s[c0 + 2*j + 1][nl] = f.y;
                }
            }
        }
    }
    __syncthreads();

    int n4 = threadIdx.x * 4;          // 0..124
    int n = n0 + n4;
    if (n + 3 < NNODE) {
        #pragma unroll
        for (int k = 0; k < 4; k++) {
            int c = threadIdx.y + k * 8;
            float bc = bias[c];
            size_t idx = (((size_t)b * CC + c) * TT + t) * NNODE + n;
            float4 xv = *reinterpret_cast<const float4*>(x + idx);
            float4 av = *reinterpret_cast<const float4*>(&s[c][n4]);
            float4 r;
            r.x = fmaxf(xv.x + bc + av.x, 0.f);
            r.y = fmaxf(xv.y + bc + av.y, 0.f);
            r.z = fmaxf(xv.z + bc + av.z, 0.f);
            r.w = fmaxf(xv.w + bc + av.w, 0.f);
            *reinterpret_cast<float4*>(out + idx) = r;
        }
    }
}

// ---------------------------------------------------------------------------
// Launch
// ---------------------------------------------------------------------------
extern "C" void kernel_launch(void* const* d_in, const int* in_sizes, int n_in,
                              void* d_out, int out_size) {
    const float* x    = (const float*)d_in[0];  // [B, C, T, N]
    const float* W    = (const float*)d_in[1];  // [C, C]
    const float* bias = (const float*)d_in[2];  // [C]
    const int*   src  = (const int*)d_in[3];    // [E]
    const int*   dst  = (const int*)d_in[4];    // [E]
    float*       out  = (float*)d_out;          // [B, C, T, N]

    k_prep<<<1, 1024>>>(src, dst);

    dim3 by((NNODE + 31) / 32, BT / 8);
    k_y<<<by, dim3(32, 8)>>>(x, W);

    k_agg<<<NNODE, 384>>>();

    k_out<<<dim3((NNODE + 127) / 128, BT), dim3(32, 8)>>>(x, bias, out);
}

// round 7
// speedup vs baseline: 1.4054x; 1.4054x over previous
#include <cuda_runtime.h>
#include <cuda_fp16.h>
#include <cuda_bf16.h>

// Problem constants
#define BB 8
#define CC 32
#define TT 12
#define NNODE 5000
#define EDGES 80000
#define FF (BB*TT*CC)       // 3072 features per node
#define BT (BB*TT)          // 96
#define EPAD (EDGES + NNODE*7 + 8)  // padded CSR capacity

// ---------------------------------------------------------------------------
// Scratch (static __device__ arrays — no allocations allowed)
// ---------------------------------------------------------------------------
__device__ __align__(16) __half g_y  [(size_t)(NNODE + 1) * FF]; // +1 dummy zero node
__device__ __align__(16) __half g_agg[(size_t)NNODE * FF];
__device__ int    g_deg_in [NNODE];
__device__ int    g_deg_out[NNODE];
__device__ int    g_cursor [NNODE];
__device__ int    g_ptr    [NNODE + 1];        // padded CSR row ptr by dst
__device__ int    g_csr_src[EPAD];             // src per edge (padded w/ NNODE)
__device__ float  g_norm_src[NNODE];
__device__ float  g_norm_dst[NNODE];

// ---------------------------------------------------------------------------
// Prep stage 1: zero counters (distributed, ~2us)
// ---------------------------------------------------------------------------
__global__ void k_zero() {
    int n = blockIdx.x * blockDim.x + threadIdx.x;
    if (n < NNODE) {
        g_deg_in[n] = 0;
        g_deg_out[n] = 0;
        g_cursor[n] = 0;
    }
}

// ---------------------------------------------------------------------------
// Prep stage 2: degree histograms via global atomics (REDG, distributed over
// all SMs and 184 L2 slices — NOT a single-block smem histogram, which
// serialized ~160K ATOMS on one SM and cost ~100us in R3/R5).
// ---------------------------------------------------------------------------
__global__ void k_deg(const int* __restrict__ src, const int* __restrict__ dst) {
    int e = blockIdx.x * blockDim.x + threadIdx.x;
    if (e < EDGES) {
        atomicAdd(&g_deg_out[src[e]], 1);
        atomicAdd(&g_deg_in [dst[e]], 1);
    }
}

// ---------------------------------------------------------------------------
// Prep stage 3: one block — norms, warp-shuffle exclusive scan of degrees
// padded to multiples of 8, pad-slot fill, dummy y row zero. Cheap (~5us):
// no histograms, no scatter here.
// ---------------------------------------------------------------------------
__global__ __launch_bounds__(1024, 1)
void k_scan1b() {
    __shared__ int s_wsum[32];
    const int tid  = threadIdx.x;
    const int lane = tid & 31;
    const int warp = tid >> 5;

    // norms (true degrees)
    for (int i = tid; i < NNODE; i += 1024) {
        g_norm_src[i] = rsqrtf((float)max(g_deg_out[i], 1));
        g_norm_dst[i] = rsqrtf((float)max(g_deg_in [i], 1));
    }

    // exclusive scan of padded degrees (5 elems/thread)
    const int base = tid * 5;
    int deg[5], pdeg[5];
    int tsum = 0;
    #pragma unroll
    for (int k = 0; k < 5; k++) {
        deg[k]  = (base + k < NNODE) ? g_deg_in[base + k] : 0;
        pdeg[k] = (deg[k] + 7) & ~7;
        tsum += pdeg[k];
    }
    int incl = tsum;
    #pragma unroll
    for (int off = 1; off < 32; off <<= 1) {
        int t = __shfl_up_sync(0xffffffffu, incl, off);
        if (lane >= off) incl += t;
    }
    if (lane == 31) s_wsum[warp] = incl;
    __syncthreads();
    if (warp == 0) {
        int w = s_wsum[lane];
        int wi = w;
        #pragma unroll
        for (int off = 1; off < 32; off <<= 1) {
            int t = __shfl_up_sync(0xffffffffu, wi, off);
            if (lane >= off) wi += t;
        }
        s_wsum[lane] = wi - w;            // exclusive warp offsets
    }
    __syncthreads();

    int run = s_wsum[warp] + incl - tsum; // exclusive prefix at base
    #pragma unroll
    for (int k = 0; k < 5; k++) {
        int idx = base + k;
        if (idx < NNODE) {
            g_ptr[idx] = run;
            for (int j = deg[k]; j < pdeg[k]; j++) g_csr_src[run + j] = NNODE;
            run += pdeg[k];
        }
    }
    if (tid == (NNODE + 4) / 5 - 1) g_ptr[NNODE] = run;   // grand total

    // zero dummy node's y row (FF halves = FF/8 uint4)
    uint4 z = make_uint4(0, 0, 0, 0);
    uint4* dy = reinterpret_cast<uint4*>(g_y + (size_t)NNODE * FF);
    for (int i = tid; i < FF / 8; i += 1024) dy[i] = z;
}

// ---------------------------------------------------------------------------
// Prep stage 4: bucket edges by dst (global atomic cursors, distributed)
// ---------------------------------------------------------------------------
__global__ void k_scatter(const int* __restrict__ src, const int* __restrict__ dst) {
    int e = blockIdx.x * blockDim.x + threadIdx.x;
    if (e < EDGES) {
        int d = dst[e];
        int pos = g_ptr[d] + atomicAdd(&g_cursor[d], 1);
        g_csr_src[pos] = src[e];
    }
}

// ---------------------------------------------------------------------------
// K_y: y[n][bt][c'] = norm_src[n] * sum_c x[b,c,t,n] * W[c][c']  (fp16 out)
// x loads coalesced over n; y stored node-major via uint4 (8 halves).
// ---------------------------------------------------------------------------
__global__ void k_y(const float* __restrict__ x, const float* __restrict__ W) {
    __shared__ float Ws[CC * CC];
    int tid = threadIdx.y * 32 + threadIdx.x;
    for (int i = tid; i < CC * CC; i += 256) Ws[i] = W[i];
    __syncthreads();

    int n  = blockIdx.x * 32 + threadIdx.x;
    int bt = blockIdx.y * 8 + threadIdx.y;
    if (n >= NNODE) return;
    int b = bt / TT, t = bt - b * TT;

    const float* xp = x + ((size_t)b * CC * TT) * NNODE + (size_t)t * NNODE + n;
    float xa[CC];
    #pragma unroll
    for (int c = 0; c < CC; c++) xa[c] = xp[(size_t)c * TT * NNODE];

    float ns = g_norm_src[n];
    uint4* yp = reinterpret_cast<uint4*>(g_y + (size_t)n * FF + (size_t)bt * CC);
    #pragma unroll
    for (int c8 = 0; c8 < CC / 8; c8++) {
        float acc[8];
        #pragma unroll
        for (int j = 0; j < 8; j++) acc[j] = 0.f;
        #pragma unroll
        for (int c = 0; c < CC; c++) {
            float xv = xa[c];
            const float* wr = &Ws[c * CC + c8 * 8];
            #pragma unroll
            for (int j = 0; j < 8; j++) acc[j] += xv * wr[j];
        }
        __half2 h[4];
        #pragma unroll
        for (int j = 0; j < 4; j++)
            h[j] = __floats2half2_rn(acc[2*j] * ns, acc[2*j+1] * ns);
        uint4 pack;
        pack.x = *reinterpret_cast<unsigned*>(&h[0]);
        pack.y = *reinterpret_cast<unsigned*>(&h[1]);
        pack.z = *reinterpret_cast<unsigned*>(&h[2]);
        pack.w = *reinterpret_cast<unsigned*>(&h[3]);
        yp[c8] = pack;
    }
}

// ---------------------------------------------------------------------------
// K_agg: agg[d] = norm_dst[d] * sum_{e in CSR[d]} y[src[e]]
// One block per dst node, 384 threads, 1 uint4 (8 halves) per thread.
// Per group of 8 edges: fp16 HADD2 accumulation (full-rate, no F2F stream),
// then one upconvert into fp32 accumulators. Edge indices are uniform-address
// L1-hit loads (no smem staging, no __syncthreads). Padding edges hit the
// zeroed dummy node row -> branch-free, 8 independent LDG.128 in flight.
// ---------------------------------------------------------------------------
__global__ __launch_bounds__(384)
void k_agg() {
    int d = blockIdx.x;
    int tid = threadIdx.x;
    int beg = g_ptr[d], end = g_ptr[d + 1];   // multiple of 8 edges

    float2 acc[4];
    #pragma unroll
    for (int j = 0; j < 4; j++) acc[j] = make_float2(0.f, 0.f);

    for (int g0 = beg; g0 < end; g0 += 8) {
        int idx[8];
        #pragma unroll
        for (int k = 0; k < 8; k++) idx[k] = g_csr_src[g0 + k];
        __half2 h[4];
        #pragma unroll
        for (int j = 0; j < 4; j++) h[j] = __floats2half2_rn(0.f, 0.f);
        #pragma unroll
        for (int k = 0; k < 8; k++) {
            const uint4* ys =
                reinterpret_cast<const uint4*>(g_y + (size_t)idx[k] * FF);
            uint4 v = ys[tid];
            h[0] = __hadd2(h[0], *reinterpret_cast<const __half2*>(&v.x));
            h[1] = __hadd2(h[1], *reinterpret_cast<const __half2*>(&v.y));
            h[2] = __hadd2(h[2], *reinterpret_cast<const __half2*>(&v.z));
            h[3] = __hadd2(h[3], *reinterpret_cast<const __half2*>(&v.w));
        }
        #pragma unroll
        for (int j = 0; j < 4; j++) {
            float2 f = __half22float2(h[j]);
            acc[j].x += f.x; acc[j].y += f.y;
        }
    }

    float nd = g_norm_dst[d];
    __half2 o[4];
    #pragma unroll
    for (int j = 0; j < 4; j++)
        o[j] = __floats2half2_rn(acc[j].x * nd, acc[j].y * nd);
    uint4 pack;
    pack.x = *reinterpret_cast<unsigned*>(&o[0]);
    pack.y = *reinterpret_cast<unsigned*>(&o[1]);
    pack.z = *reinterpret_cast<unsigned*>(&o[2]);
    pack.w = *reinterpret_cast<unsigned*>(&o[3]);
    reinterpret_cast<uint4*>(g_agg + (size_t)d * FF)[tid] = pack;
}

// ---------------------------------------------------------------------------
// K_out: out[b,c,t,n] = relu(x[b,c,t,n] + bias[c] + agg[n][b][t][c])
// 128-node tiles, float4 LDG/STG for x/out; agg staged via smem transpose.
// ---------------------------------------------------------------------------
__global__ __launch_bounds__(256)
void k_out(const float* __restrict__ x, const float* __restrict__ bias,
           float* __restrict__ out) {
    __shared__ float s[CC][132];   // [c][n], row stride 132
    int bt = blockIdx.y;
    int b = bt / TT, t = bt - b * TT;
    int n0 = blockIdx.x * 128;
    int tid = threadIdx.y * 32 + threadIdx.x;

    // Stage agg[n0..n0+127][bt*32..+32) -> s[c][nl]. Each node row = 4 uint4.
    {
        int nl   = tid >> 1;           // 0..127
        int part = tid & 1;            // halves of the 32-c row
        int n = n0 + nl;
        if (n < NNODE) {
            const uint4* ar =
                reinterpret_cast<const uint4*>(g_agg + (size_t)n * FF + (size_t)bt * CC);
            #pragma unroll
            for (int q = 0; q < 2; q++) {
                uint4 v = ar[part * 2 + q];
                int c0 = part * 16 + q * 8;
                const unsigned* u = &v.x;
                #pragma unroll
                for (int j = 0; j < 4; j++) {
                    float2 f = __half22float2(*reinterpret_cast<const __half2*>(&u[j]));
                    s[c0 + 2*j    ][nl] = f.x;
                    s[c0 + 2*j + 1][nl] = f.y;
                }
            }
        }
    }
    __syncthreads();

    int n4 = threadIdx.x * 4;          // 0..124
    int n = n0 + n4;
    if (n + 3 < NNODE) {
        #pragma unroll
        for (int k = 0; k < 4; k++) {
            int c = threadIdx.y + k * 8;
            float bc = bias[c];
            size_t idx = (((size_t)b * CC + c) * TT + t) * NNODE + n;
            float4 xv = *reinterpret_cast<const float4*>(x + idx);
            float4 av = *reinterpret_cast<const float4*>(&s[c][n4]);
            float4 r;
            r.x = fmaxf(xv.x + bc + av.x, 0.f);
            r.y = fmaxf(xv.y + bc + av.y, 0.f);
            r.z = fmaxf(xv.z + bc + av.z, 0.f);
            r.w = fmaxf(xv.w + bc + av.w, 0.f);
            *reinterpret_cast<float4*>(out + idx) = r;
        }
    }
}

// ---------------------------------------------------------------------------
// Launch
// ---------------------------------------------------------------------------
extern "C" void kernel_launch(void* const* d_in, const int* in_sizes, int n_in,
                              void* d_out, int out_size) {
    const float* x    = (const float*)d_in[0];  // [B, C, T, N]
    const float* W    = (const float*)d_in[1];  // [C, C]
    const float* bias = (const float*)d_in[2];  // [C]
    const int*   src  = (const int*)d_in[3];    // [E]
    const int*   dst  = (const int*)d_in[4];    // [E]
    float*       out  = (float*)d_out;          // [B, C, T, N]

    k_zero<<<(NNODE + 255) / 256, 256>>>();
    k_deg<<<(EDGES + 255) / 256, 256>>>(src, dst);
    k_scan1b<<<1, 1024>>>();
    k_scatter<<<(EDGES + 255) / 256, 256>>>(src, dst);

    dim3 by((NNODE + 31) / 32, BT / 8);
    k_y<<<by, dim3(32, 8)>>>(x, W);

    k_agg<<<NNODE, 384>>>();

    k_out<<<dim3((NNODE + 127) / 128, BT), dim3(32, 8)>>>(x, bias, out);
}

// round 8
// speedup vs baseline: 1.4493x; 1.0313x over previous
#include <cuda_runtime.h>
#include <cuda_fp16.h>
#include <cuda_bf16.h>

// Problem constants
#define BB 8
#define CC 32
#define TT 12
#define NNODE 5000
#define EDGES 80000
#define FF (BB*TT*CC)       // 3072 features per node
#define BT (BB*TT)          // 96
#define EPAD (EDGES + NNODE*7 + 8)  // padded CSR capacity

#define NTILES 157                  // ceil(5000/32)
#define YBLOCKS (NTILES * (BT/8))   // 157*12 = 1884 y-blocks
#define SCBLOCKS 40                 // scatter blocks appended to k_y grid

// ---------------------------------------------------------------------------
// Scratch (static __device__ arrays — no allocations allowed).
// Counters are zeroed at the END of each call (in k_agg, after last use);
// first call relies on guaranteed zero-initialization of __device__ globals.
// ---------------------------------------------------------------------------
__device__ __align__(16) __half g_y  [(size_t)(NNODE + 1) * FF]; // +1 dummy zero node
__device__ __align__(16) __half g_agg[(size_t)NNODE * FF];
__device__ int    g_deg_in [NNODE];   // zero on entry (see above)
__device__ int    g_deg_out[NNODE];
__device__ int    g_cursor [NNODE];
__device__ int    g_ptr    [NNODE + 1];          // padded CSR row ptr by dst
__device__ __align__(16) int g_csr_src[EPAD];    // src per edge (padded w/ NNODE)
__device__ float  g_norm_src[NNODE];
__device__ float  g_norm_dst[NNODE];

// ---------------------------------------------------------------------------
// K1: degree histograms via distributed global atomics (REDG over 184 L2
// slices — never a single-block smem histogram, which costs ~100us).
// ---------------------------------------------------------------------------
__global__ void k_deg(const int* __restrict__ src, const int* __restrict__ dst) {
    int e = blockIdx.x * blockDim.x + threadIdx.x;
    if (e < EDGES) {
        atomicAdd(&g_deg_out[src[e]], 1);
        atomicAdd(&g_deg_in [dst[e]], 1);
    }
}

// ---------------------------------------------------------------------------
// K2: one block — norms, warp-shuffle exclusive scan of degrees padded to
// multiples of 8, pad-slot fill, dummy y row zero.
// ---------------------------------------------------------------------------
__global__ __launch_bounds__(1024, 1)
void k_scan1b() {
    __shared__ int s_wsum[32];
    const int tid  = threadIdx.x;
    const int lane = tid & 31;
    const int warp = tid >> 5;

    // norms (true degrees)
    for (int i = tid; i < NNODE; i += 1024) {
        g_norm_src[i] = rsqrtf((float)max(g_deg_out[i], 1));
        g_norm_dst[i] = rsqrtf((float)max(g_deg_in [i], 1));
    }

    // exclusive scan of padded degrees (5 elems/thread)
    const int base = tid * 5;
    int deg[5], pdeg[5];
    int tsum = 0;
    #pragma unroll
    for (int k = 0; k < 5; k++) {
        deg[k]  = (base + k < NNODE) ? g_deg_in[base + k] : 0;
        pdeg[k] = (deg[k] + 7) & ~7;
        tsum += pdeg[k];
    }
    int incl = tsum;
    #pragma unroll
    for (int off = 1; off < 32; off <<= 1) {
        int t = __shfl_up_sync(0xffffffffu, incl, off);
        if (lane >= off) incl += t;
    }
    if (lane == 31) s_wsum[warp] = incl;
    __syncthreads();
    if (warp == 0) {
        int w = s_wsum[lane];
        int wi = w;
        #pragma unroll
        for (int off = 1; off < 32; off <<= 1) {
            int t = __shfl_up_sync(0xffffffffu, wi, off);
            if (lane >= off) wi += t;
        }
        s_wsum[lane] = wi - w;            // exclusive warp offsets
    }
    __syncthreads();

    int run = s_wsum[warp] + incl - tsum; // exclusive prefix at base
    #pragma unroll
    for (int k = 0; k < 5; k++) {
        int idx = base + k;
        if (idx < NNODE) {
            g_ptr[idx] = run;
            for (int j = deg[k]; j < pdeg[k]; j++) g_csr_src[run + j] = NNODE;
            run += pdeg[k];
        }
    }
    if (tid == (NNODE + 4) / 5 - 1) g_ptr[NNODE] = run;   // grand total

    // zero dummy node's y row (FF halves = FF/8 uint4)
    uint4 z = make_uint4(0, 0, 0, 0);
    uint4* dy = reinterpret_cast<uint4*>(g_y + (size_t)NNODE * FF);
    for (int i = tid; i < FF / 8; i += 1024) dy[i] = z;
}

// ---------------------------------------------------------------------------
// K3: fused y-GEMM + CSR scatter (block-granular split, saves one launch).
// Blocks [0, YBLOCKS): y[n][bt][c'] = norm_src[n] * sum_c x[b,c,t,n]*W[c][c']
// Blocks [YBLOCKS, YBLOCKS+SCBLOCKS): bucket edges by dst via atomic cursors.
// ---------------------------------------------------------------------------
__global__ __launch_bounds__(256)
void k_y_scatter(const float* __restrict__ x, const float* __restrict__ W,
                 const int* __restrict__ src, const int* __restrict__ dst) {
    if (blockIdx.x >= YBLOCKS) {
        // ---- scatter branch (40 blocks * 256 threads, ~8 edges each) ----
        int e0 = (blockIdx.x - YBLOCKS) * 256 + threadIdx.x;
        for (int e = e0; e < EDGES; e += SCBLOCKS * 256) {
            int d = dst[e];
            int pos = g_ptr[d] + atomicAdd(&g_cursor[d], 1);
            g_csr_src[pos] = src[e];
        }
        return;
    }

    // ---- y branch ----
    __shared__ float Ws[CC * CC];
    int tid = threadIdx.x;
    int tx = tid & 31, ty = tid >> 5;
    for (int i = tid; i < CC * CC; i += 256) Ws[i] = W[i];
    __syncthreads();

    int nt  = blockIdx.x % NTILES;
    int btt = blockIdx.x / NTILES;
    int n  = nt * 32 + tx;
    int bt = btt * 8 + ty;
    if (n >= NNODE) return;
    int b = bt / TT, t = bt - b * TT;

    const float* xp = x + ((size_t)b * CC * TT) * NNODE + (size_t)t * NNODE + n;
    float xa[CC];
    #pragma unroll
    for (int c = 0; c < CC; c++) xa[c] = xp[(size_t)c * TT * NNODE];

    float ns = g_norm_src[n];
    uint4* yp = reinterpret_cast<uint4*>(g_y + (size_t)n * FF + (size_t)bt * CC);
    #pragma unroll
    for (int c8 = 0; c8 < CC / 8; c8++) {
        float acc[8];
        #pragma unroll
        for (int j = 0; j < 8; j++) acc[j] = 0.f;
        #pragma unroll
        for (int c = 0; c < CC; c++) {
            float xv = xa[c];
            const float* wr = &Ws[c * CC + c8 * 8];
            #pragma unroll
            for (int j = 0; j < 8; j++) acc[j] += xv * wr[j];
        }
        __half2 h[4];
        #pragma unroll
        for (int j = 0; j < 4; j++)
            h[j] = __floats2half2_rn(acc[2*j] * ns, acc[2*j+1] * ns);
        uint4 pack;
        pack.x = *reinterpret_cast<unsigned*>(&h[0]);
        pack.y = *reinterpret_cast<unsigned*>(&h[1]);
        pack.z = *reinterpret_cast<unsigned*>(&h[2]);
        pack.w = *reinterpret_cast<unsigned*>(&h[3]);
        yp[c8] = pack;
    }
}

// ---------------------------------------------------------------------------
// K4: agg[d] = norm_dst[d] * sum_{e in CSR[d]} y[src[e]]
// One block per dst node, 384 threads, 1 uint4 (8 halves) per thread.
// Per group of 8 edges: indices via two aligned int4 loads, fp16 HADD2
// accumulation (full-rate), one fp32 upconvert per group. Padding edges hit
// the zeroed dummy row. Also zeroes this node's counters for the NEXT call.
// ---------------------------------------------------------------------------
__global__ __launch_bounds__(384)
void k_agg() {
    int d = blockIdx.x;
    int tid = threadIdx.x;

    // counters are dead after k_y_scatter: reset for next graph replay
    if (tid == 0) {
        g_deg_in[d] = 0;
        g_deg_out[d] = 0;
        g_cursor[d] = 0;
    }

    int beg = g_ptr[d], end = g_ptr[d + 1];   // multiple of 8 edges, 32B-aligned

    float2 acc[4];
    #pragma unroll
    for (int j = 0; j < 4; j++) acc[j] = make_float2(0.f, 0.f);

    for (int g0 = beg; g0 < end; g0 += 8) {
        int4 i0 = *reinterpret_cast<const int4*>(&g_csr_src[g0]);
        int4 i1 = *reinterpret_cast<const int4*>(&g_csr_src[g0 + 4]);
        int idx[8] = { i0.x, i0.y, i0.z, i0.w, i1.x, i1.y, i1.z, i1.w };
        __half2 h[4];
        #pragma unroll
        for (int j = 0; j < 4; j++) h[j] = __floats2half2_rn(0.f, 0.f);
        #pragma unroll
        for (int k = 0; k < 8; k++) {
            const uint4* ys =
                reinterpret_cast<const uint4*>(g_y + (size_t)idx[k] * FF);
            uint4 v = ys[tid];
            h[0] = __hadd2(h[0], *reinterpret_cast<const __half2*>(&v.x));
            h[1] = __hadd2(h[1], *reinterpret_cast<const __half2*>(&v.y));
            h[2] = __hadd2(h[2], *reinterpret_cast<const __half2*>(&v.z));
            h[3] = __hadd2(h[3], *reinterpret_cast<const __half2*>(&v.w));
        }
        #pragma unroll
        for (int j = 0; j < 4; j++) {
            float2 f = __half22float2(h[j]);
            acc[j].x += f.x; acc[j].y += f.y;
        }
    }

    float nd = g_norm_dst[d];
    __half2 o[4];
    #pragma unroll
    for (int j = 0; j < 4; j++)
        o[j] = __floats2half2_rn(acc[j].x * nd, acc[j].y * nd);
    uint4 pack;
    pack.x = *reinterpret_cast<unsigned*>(&o[0]);
    pack.y = *reinterpret_cast<unsigned*>(&o[1]);
    pack.z = *reinterpret_cast<unsigned*>(&o[2]);
    pack.w = *reinterpret_cast<unsigned*>(&o[3]);
    reinterpret_cast<uint4*>(g_agg + (size_t)d * FF)[tid] = pack;
}

// ---------------------------------------------------------------------------
// K5: out[b,c,t,n] = relu(x[b,c,t,n] + bias[c] + agg[n][b][t][c])
// 256-node tiles, 512 threads; float4 LDG/STG for x/out; agg staged via
// padded smem transpose.
// ---------------------------------------------------------------------------
#define ONODES 256
__global__ __launch_bounds__(512)
void k_out(const float* __restrict__ x, const float* __restrict__ bias,
           float* __restrict__ out) {
    __shared__ float s[CC][ONODES + 4];   // stride 260 floats
    int bt = blockIdx.y;
    int b = bt / TT, t = bt - b * TT;
    int n0 = blockIdx.x * ONODES;
    int tid = threadIdx.y * 64 + threadIdx.x;

    // Stage agg[n0..n0+255][bt*32..+32) -> s[c][nl]. Each node row = 4 uint4.
    {
        int nl   = tid >> 1;           // 0..255
        int part = tid & 1;            // halves of the 32-c row
        int n = n0 + nl;
        if (n < NNODE) {
            const uint4* ar =
                reinterpret_cast<const uint4*>(g_agg + (size_t)n * FF + (size_t)bt * CC);
            #pragma unroll
            for (int q = 0; q < 2; q++) {
                uint4 v = ar[part * 2 + q];
                int c0 = part * 16 + q * 8;
                const unsigned* u = &v.x;
                #pragma unroll
                for (int j = 0; j < 4; j++) {
                    float2 f = __half22float2(*reinterpret_cast<const __half2*>(&u[j]));
                    s[c0 + 2*j    ][nl] = f.x;
                    s[c0 + 2*j + 1][nl] = f.y;
                }
            }
        }
    }
    __syncthreads();

    int n4 = threadIdx.x * 4;          // 0..252
    int n = n0 + n4;
    if (n < NNODE) {                   // NNODE % 4 == 0, float4-safe
        #pragma unroll
        for (int k = 0; k < 4; k++) {
            int c = threadIdx.y + k * 8;
            float bc = bias[c];
            size_t idx = (((size_t)b * CC + c) * TT + t) * NNODE + n;
            float4 xv = *reinterpret_cast<const float4*>(x + idx);
            float4 av = *reinterpret_cast<const float4*>(&s[c][n4]);
            float4 r;
            r.x = fmaxf(xv.x + bc + av.x, 0.f);
            r.y = fmaxf(xv.y + bc + av.y, 0.f);
            r.z = fmaxf(xv.z + bc + av.z, 0.f);
            r.w = fmaxf(xv.w + bc + av.w, 0.f);
            *reinterpret_cast<float4*>(out + idx) = r;
        }
    }
}

// ---------------------------------------------------------------------------
// Launch: 5 kernels (was 7)
// ---------------------------------------------------------------------------
extern "C" void kernel_launch(void* const* d_in, const int* in_sizes, int n_in,
                              void* d_out, int out_size) {
    const float* x    = (const float*)d_in[0];  // [B, C, T, N]
    const float* W    = (const float*)d_in[1];  // [C, C]
    const float* bias = (const float*)d_in[2];  // [C]
    const int*   src  = (const int*)d_in[3];    // [E]
    const int*   dst  = (const int*)d_in[4];    // [E]
    float*       out  = (float*)d_out;          // [B, C, T, N]

    k_deg<<<(EDGES + 255) / 256, 256>>>(src, dst);
    k_scan1b<<<1, 1024>>>();
    k_y_scatter<<<YBLOCKS + SCBLOCKS, 256>>>(x, W, src, dst);
    k_agg<<<NNODE, 384>>>();
    k_out<<<dim3((NNODE + ONODES - 1) / ONODES, BT), dim3(64, 8)>>>(x, bias, out);
}

// round 9
// speedup vs baseline: 1.4699x; 1.0142x over previous
#include <cuda_runtime.h>
#include <cuda_fp16.h>
#include <cuda_bf16.h>

// Problem constants
#define BB 8
#define CC 32
#define TT 12
#define NNODE 5000
#define EDGES 80000
#define FF (BB*TT*CC)       // 3072 features per node
#define BT (BB*TT)          // 96
#define EPAD (EDGES + NNODE*7 + 8)  // padded CSR capacity

#define NTILES 157                  // ceil(5000/32)
#define YBLOCKS (NTILES * (BT/8))   // 157*12 = 1884 y-blocks
#define SCBLOCKS 40                 // scatter blocks appended to k_y grid
#define AGGBLOCKS 592               // persistent k_agg blocks (~4/SM)

// ---------------------------------------------------------------------------
// Scratch (static __device__ arrays — no allocations allowed).
// Counters zeroed after last use each call; first call relies on zero-init.
// ---------------------------------------------------------------------------
__device__ __align__(16) __half g_y  [(size_t)(NNODE + 1) * FF]; // +1 dummy zero node
__device__ __align__(16) __half g_agg[(size_t)NNODE * FF];
__device__ int    g_deg_in [NNODE];
__device__ int    g_deg_out[NNODE];
__device__ int    g_cursor [NNODE];
__device__ int    g_ptr    [NNODE + 1];          // padded CSR row ptr by dst
__device__ __align__(16) int g_csr_src[EPAD];    // src per edge (padded w/ NNODE)
__device__ float  g_norm_src[NNODE];
__device__ float  g_norm_dst[NNODE];
__device__ int    g_work;                        // k_agg work-stealing counter

// ---------------------------------------------------------------------------
// K1: degree histograms via distributed global atomics (REDG over L2 slices)
// ---------------------------------------------------------------------------
__global__ void k_deg(const int* __restrict__ src, const int* __restrict__ dst) {
    int e = blockIdx.x * blockDim.x + threadIdx.x;
    if (e < EDGES) {
        atomicAdd(&g_deg_out[src[e]], 1);
        atomicAdd(&g_deg_in [dst[e]], 1);
    }
}

// ---------------------------------------------------------------------------
// K2: one block — norms, warp-shuffle exclusive scan of degrees padded to
// multiples of 8, pad-slot fill, dummy y row zero, work-counter reset.
// ---------------------------------------------------------------------------
__global__ __launch_bounds__(1024, 1)
void k_scan1b() {
    __shared__ int s_wsum[32];
    const int tid  = threadIdx.x;
    const int lane = tid & 31;
    const int warp = tid >> 5;

    if (tid == 0) g_work = 0;   // reset k_agg work counter for this replay

    // norms (true degrees)
    for (int i = tid; i < NNODE; i += 1024) {
        g_norm_src[i] = rsqrtf((float)max(g_deg_out[i], 1));
        g_norm_dst[i] = rsqrtf((float)max(g_deg_in [i], 1));
    }

    // exclusive scan of padded degrees (5 elems/thread)
    const int base = tid * 5;
    int deg[5], pdeg[5];
    int tsum = 0;
    #pragma unroll
    for (int k = 0; k < 5; k++) {
        deg[k]  = (base + k < NNODE) ? g_deg_in[base + k] : 0;
        pdeg[k] = (deg[k] + 7) & ~7;
        tsum += pdeg[k];
    }
    int incl = tsum;
    #pragma unroll
    for (int off = 1; off < 32; off <<= 1) {
        int t = __shfl_up_sync(0xffffffffu, incl, off);
        if (lane >= off) incl += t;
    }
    if (lane == 31) s_wsum[warp] = incl;
    __syncthreads();
    if (warp == 0) {
        int w = s_wsum[lane];
        int wi = w;
        #pragma unroll
        for (int off = 1; off < 32; off <<= 1) {
            int t = __shfl_up_sync(0xffffffffu, wi, off);
            if (lane >= off) wi += t;
        }
        s_wsum[lane] = wi - w;            // exclusive warp offsets
    }
    __syncthreads();

    int run = s_wsum[warp] + incl - tsum; // exclusive prefix at base
    #pragma unroll
    for (int k = 0; k < 5; k++) {
        int idx = base + k;
        if (idx < NNODE) {
            g_ptr[idx] = run;
            for (int j = deg[k]; j < pdeg[k]; j++) g_csr_src[run + j] = NNODE;
            run += pdeg[k];
        }
    }
    if (tid == (NNODE + 4) / 5 - 1) g_ptr[NNODE] = run;   // grand total

    // zero dummy node's y row (FF halves = FF/8 uint4)
    uint4 z = make_uint4(0, 0, 0, 0);
    uint4* dy = reinterpret_cast<uint4*>(g_y + (size_t)NNODE * FF);
    for (int i = tid; i < FF / 8; i += 1024) dy[i] = z;
}

// ---------------------------------------------------------------------------
// K3: fused y-GEMM + CSR scatter (block-granular split).
// Blocks [0, YBLOCKS): y[n][bt][c'] = norm_src[n] * sum_c x[b,c,t,n]*W[c][c']
// Blocks [YBLOCKS, ...): bucket edges by dst via atomic cursors.
// x read with __ldcs (streaming — no reuse here, keep L2 for y).
// ---------------------------------------------------------------------------
__global__ __launch_bounds__(256)
void k_y_scatter(const float* __restrict__ x, const float* __restrict__ W,
                 const int* __restrict__ src, const int* __restrict__ dst) {
    if (blockIdx.x >= YBLOCKS) {
        int e0 = (blockIdx.x - YBLOCKS) * 256 + threadIdx.x;
        for (int e = e0; e < EDGES; e += SCBLOCKS * 256) {
            int d = dst[e];
            int pos = g_ptr[d] + atomicAdd(&g_cursor[d], 1);
            g_csr_src[pos] = src[e];
        }
        return;
    }

    __shared__ float Ws[CC * CC];
    int tid = threadIdx.x;
    int tx = tid & 31, ty = tid >> 5;
    for (int i = tid; i < CC * CC; i += 256) Ws[i] = W[i];
    __syncthreads();

    int nt  = blockIdx.x % NTILES;
    int btt = blockIdx.x / NTILES;
    int n  = nt * 32 + tx;
    int bt = btt * 8 + ty;
    if (n >= NNODE) return;
    int b = bt / TT, t = bt - b * TT;

    const float* xp = x + ((size_t)b * CC * TT) * NNODE + (size_t)t * NNODE + n;
    float xa[CC];
    #pragma unroll
    for (int c = 0; c < CC; c++) xa[c] = __ldcs(xp + (size_t)c * TT * NNODE);

    float ns = g_norm_src[n];
    uint4* yp = reinterpret_cast<uint4*>(g_y + (size_t)n * FF + (size_t)bt * CC);
    #pragma unroll
    for (int c8 = 0; c8 < CC / 8; c8++) {
        float acc[8];
        #pragma unroll
        for (int j = 0; j < 8; j++) acc[j] = 0.f;
        #pragma unroll
        for (int c = 0; c < CC; c++) {
            float xv = xa[c];
            const float* wr = &Ws[c * CC + c8 * 8];
            #pragma unroll
            for (int j = 0; j < 8; j++) acc[j] += xv * wr[j];
        }
        __half2 h[4];
        #pragma unroll
        for (int j = 0; j < 4; j++)
            h[j] = __floats2half2_rn(acc[2*j] * ns, acc[2*j+1] * ns);
        uint4 pack;
        pack.x = *reinterpret_cast<unsigned*>(&h[0]);
        pack.y = *reinterpret_cast<unsigned*>(&h[1]);
        pack.z = *reinterpret_cast<unsigned*>(&h[2]);
        pack.w = *reinterpret_cast<unsigned*>(&h[3]);
        yp[c8] = pack;
    }
}

// ---------------------------------------------------------------------------
// K4: persistent work-stealing aggregation. 592 resident blocks grab dst
// nodes from g_work (deterministic: each node processed by exactly one
// block; result independent of assignment). Per node: fp16 HADD2 groups of
// 8 edges, fp32 upconvert per group. Kills wave-quantization + degree tail.
// Also zeroes that node's counters for the next replay.
// ---------------------------------------------------------------------------
__global__ __launch_bounds__(384)
void k_agg() {
    __shared__ int s_d;
    int tid = threadIdx.x;

    while (true) {
        if (tid == 0) s_d = atomicAdd(&g_work, 1);
        __syncthreads();
        int d = s_d;
        __syncthreads();
        if (d >= NNODE) return;

        if (tid == 0) {
            g_deg_in[d] = 0;
            g_deg_out[d] = 0;
            g_cursor[d] = 0;
        }

        int beg = g_ptr[d], end = g_ptr[d + 1];   // multiple of 8, 32B-aligned

        float2 acc[4];
        #pragma unroll
        for (int j = 0; j < 4; j++) acc[j] = make_float2(0.f, 0.f);

        for (int g0 = beg; g0 < end; g0 += 8) {
            int4 i0 = *reinterpret_cast<const int4*>(&g_csr_src[g0]);
            int4 i1 = *reinterpret_cast<const int4*>(&g_csr_src[g0 + 4]);
            int idx[8] = { i0.x, i0.y, i0.z, i0.w, i1.x, i1.y, i1.z, i1.w };
            __half2 h[4];
            #pragma unroll
            for (int j = 0; j < 4; j++) h[j] = __floats2half2_rn(0.f, 0.f);
            #pragma unroll
            for (int k = 0; k < 8; k++) {
                const uint4* ys =
                    reinterpret_cast<const uint4*>(g_y + (size_t)idx[k] * FF);
                uint4 v = ys[tid];
                h[0] = __hadd2(h[0], *reinterpret_cast<const __half2*>(&v.x));
                h[1] = __hadd2(h[1], *reinterpret_cast<const __half2*>(&v.y));
                h[2] = __hadd2(h[2], *reinterpret_cast<const __half2*>(&v.z));
                h[3] = __hadd2(h[3], *reinterpret_cast<const __half2*>(&v.w));
            }
            #pragma unroll
            for (int j = 0; j < 4; j++) {
                float2 f = __half22float2(h[j]);
                acc[j].x += f.x; acc[j].y += f.y;
            }
        }

        float nd = g_norm_dst[d];
        __half2 o[4];
        #pragma unroll
        for (int j = 0; j < 4; j++)
            o[j] = __floats2half2_rn(acc[j].x * nd, acc[j].y * nd);
        uint4 pack;
        pack.x = *reinterpret_cast<unsigned*>(&o[0]);
        pack.y = *reinterpret_cast<unsigned*>(&o[1]);
        pack.z = *reinterpret_cast<unsigned*>(&o[2]);
        pack.w = *reinterpret_cast<unsigned*>(&o[3]);
        reinterpret_cast<uint4*>(g_agg + (size_t)d * FF)[tid] = pack;
    }
}

// ---------------------------------------------------------------------------
// K5: out[b,c,t,n] = relu(x[b,c,t,n] + bias[c] + agg[n][b][t][c])
// 256-node tiles, 512 threads, 3 blocks/SM; x via __ldcs (stream), out via
// __stcs (never re-read); agg via default policy (L2-hit from K4).
// ---------------------------------------------------------------------------
#define ONODES 256
__global__ __launch_bounds__(512, 3)
void k_out(const float* __restrict__ x, const float* __restrict__ bias,
           float* __restrict__ out) {
    __shared__ float s[CC][ONODES + 4];   // stride 260 floats
    int bt = blockIdx.y;
    int b = bt / TT, t = bt - b * TT;
    int n0 = blockIdx.x * ONODES;
    int tid = threadIdx.y * 64 + threadIdx.x;

    // Stage agg[n0..n0+255][bt*32..+32) -> s[c][nl]. Each node row = 4 uint4.
    {
        int nl   = tid >> 1;           // 0..255
        int part = tid & 1;            // halves of the 32-c row
        int n = n0 + nl;
        if (n < NNODE) {
            const uint4* ar =
                reinterpret_cast<const uint4*>(g_agg + (size_t)n * FF + (size_t)bt * CC);
            #pragma unroll
            for (int q = 0; q < 2; q++) {
                uint4 v = ar[part * 2 + q];
                int c0 = part * 16 + q * 8;
                const unsigned* u = &v.x;
                #pragma unroll
                for (int j = 0; j < 4; j++) {
                    float2 f = __half22float2(*reinterpret_cast<const __half2*>(&u[j]));
                    s[c0 + 2*j    ][nl] = f.x;
                    s[c0 + 2*j + 1][nl] = f.y;
                }
            }
        }
    }
    __syncthreads();

    int n4 = threadIdx.x * 4;          // 0..252
    int n = n0 + n4;
    if (n < NNODE) {                   // NNODE % 4 == 0, float4-safe
        #pragma unroll
        for (int k = 0; k < 4; k++) {
            int c = threadIdx.y + k * 8;
            float bc = bias[c];
            size_t idx = (((size_t)b * CC + c) * TT + t) * NNODE + n;
            float4 xv = __ldcs(reinterpret_cast<const float4*>(x + idx));
            float4 av = *reinterpret_cast<const float4*>(&s[c][n4]);
            float4 r;
            r.x = fmaxf(xv.x + bc + av.x, 0.f);
            r.y = fmaxf(xv.y + bc + av.y, 0.f);
            r.z = fmaxf(xv.z + bc + av.z, 0.f);
            r.w = fmaxf(xv.w + bc + av.w, 0.f);
            __stcs(reinterpret_cast<float4*>(out + idx), r);
        }
    }
}

// ---------------------------------------------------------------------------
// Launch: 5 kernels
// ---------------------------------------------------------------------------
extern "C" void kernel_launch(void* const* d_in, const int* in_sizes, int n_in,
                              void* d_out, int out_size) {
    const float* x    = (const float*)d_in[0];  // [B, C, T, N]
    const float* W    = (const float*)d_in[1];  // [C, C]
    const float* bias = (const float*)d_in[2];  // [C]
    const int*   src  = (const int*)d_in[3];    // [E]
    const int*   dst  = (const int*)d_in[4];    // [E]
    float*       out  = (float*)d_out;          // [B, C, T, N]

    k_deg<<<(EDGES + 255) / 256, 256>>>(src, dst);
    k_scan1b<<<1, 1024>>>();
    k_y_scatter<<<YBLOCKS + SCBLOCKS, 256>>>(x, W, src, dst);
    k_agg<<<AGGBLOCKS, 384>>>();
    k_out<<<dim3((NNODE + ONODES - 1) / ONODES, BT), dim3(64, 8)>>>(x, bias, out);
}

// round 10
// speedup vs baseline: 1.6125x; 1.0970x over previous
#include <cuda_runtime.h>
#include <cuda_fp16.h>
#include <cuda_bf16.h>

// Problem constants
#define BB 8
#define CC 32
#define TT 12
#define NNODE 5000
#define EDGES 80000
#define FF (BB*TT*CC)       // 3072 features per node
#define BT (BB*TT)          // 96
#define EPAD (EDGES + NNODE*3 + 8)  // padded CSR capacity (pad-to-4)

#define NTILES 157                  // ceil(5000/32)
#define YBLOCKS (NTILES * (BT/8))   // 157*12 = 1884 y-blocks
#define SCBLOCKS 40                 // scatter blocks appended to k_y grid
#define AGGBLOCKS 592               // persistent k_agg blocks (~4/SM)

// ---------------------------------------------------------------------------
// Scratch (static __device__ arrays — no allocations allowed).
// Counters zeroed after last use each call; first call relies on zero-init.
// ---------------------------------------------------------------------------
__device__ __align__(16) __half g_y  [(size_t)(NNODE + 1) * FF]; // +1 dummy zero node
__device__ __align__(16) __half g_agg[(size_t)NNODE * FF];
__device__ int    g_deg_in [NNODE];
__device__ int    g_deg_out[NNODE];
__device__ int    g_cursor [NNODE];
__device__ int    g_ptr    [NNODE + 1];          // padded CSR row ptr by dst
__device__ __align__(16) int g_csr_src[EPAD];    // src per edge (padded w/ NNODE)
__device__ float  g_norm_src[NNODE];
__device__ float  g_norm_dst[NNODE];
__device__ int    g_work;                        // k_agg work-stealing counter

// Packed 2xfp32 FMA (Blackwell FFMA2 — only reachable via PTX f32x2)
__device__ __forceinline__ unsigned long long ffma2(
    unsigned long long a, unsigned long long b, unsigned long long c) {
    unsigned long long d;
    asm("fma.rn.f32x2 %0, %1, %2, %3;" : "=l"(d) : "l"(a), "l"(b), "l"(c));
    return d;
}

// ---------------------------------------------------------------------------
// K1: degree histograms via distributed global atomics
// ---------------------------------------------------------------------------
__global__ void k_deg(const int* __restrict__ src, const int* __restrict__ dst) {
    int e = blockIdx.x * blockDim.x + threadIdx.x;
    if (e < EDGES) {
        atomicAdd(&g_deg_out[src[e]], 1);
        atomicAdd(&g_deg_in [dst[e]], 1);
    }
}

// ---------------------------------------------------------------------------
// K2: one block — norms, warp-shuffle exclusive scan of degrees padded to
// multiples of 4, pad-slot fill, dummy y row zero, work-counter reset.
// ---------------------------------------------------------------------------
__global__ __launch_bounds__(1024, 1)
void k_scan1b() {
    __shared__ int s_wsum[32];
    const int tid  = threadIdx.x;
    const int lane = tid & 31;
    const int warp = tid >> 5;

    if (tid == 0) g_work = 0;   // reset k_agg work counter for this replay

    for (int i = tid; i < NNODE; i += 1024) {
        g_norm_src[i] = rsqrtf((float)max(g_deg_out[i], 1));
        g_norm_dst[i] = rsqrtf((float)max(g_deg_in [i], 1));
    }

    const int base = tid * 5;
    int deg[5], pdeg[5];
    int tsum = 0;
    #pragma unroll
    for (int k = 0; k < 5; k++) {
        deg[k]  = (base + k < NNODE) ? g_deg_in[base + k] : 0;
        pdeg[k] = (deg[k] + 3) & ~3;
        tsum += pdeg[k];
    }
    int incl = tsum;
    #pragma unroll
    for (int off = 1; off < 32; off <<= 1) {
        int t = __shfl_up_sync(0xffffffffu, incl, off);
        if (lane >= off) incl += t;
    }
    if (lane == 31) s_wsum[warp] = incl;
    __syncthreads();
    if (warp == 0) {
        int w = s_wsum[lane];
        int wi = w;
        #pragma unroll
        for (int off = 1; off < 32; off <<= 1) {
            int t = __shfl_up_sync(0xffffffffu, wi, off);
            if (lane >= off) wi += t;
        }
        s_wsum[lane] = wi - w;
    }
    __syncthreads();

    int run = s_wsum[warp] + incl - tsum;
    #pragma unroll
    for (int k = 0; k < 5; k++) {
        int idx = base + k;
        if (idx < NNODE) {
            g_ptr[idx] = run;
            for (int j = deg[k]; j < pdeg[k]; j++) g_csr_src[run + j] = NNODE;
            run += pdeg[k];
        }
    }
    if (tid == (NNODE + 4) / 5 - 1) g_ptr[NNODE] = run;

    uint4 z = make_uint4(0, 0, 0, 0);
    uint4* dy = reinterpret_cast<uint4*>(g_y + (size_t)NNODE * FF);
    for (int i = tid; i < FF / 8; i += 1024) dy[i] = z;
}

// ---------------------------------------------------------------------------
// K3: fused y-GEMM + CSR scatter.
// y branch uses packed f32x2 FMA: c-outer loop, 16 packed accumulators
// (all 32 outputs), xv broadcast-packed once per c, W as ulonglong2 pairs
// from smem (LDS.128 broadcast). Halves FMA-pipe issue vs scalar FFMA.
// ---------------------------------------------------------------------------
__global__ __launch_bounds__(256)
void k_y_scatter(const float* __restrict__ x, const float* __restrict__ W,
                 const int* __restrict__ src, const int* __restrict__ dst) {
    if (blockIdx.x >= YBLOCKS) {
        int e0 = (blockIdx.x - YBLOCKS) * 256 + threadIdx.x;
        for (int e = e0; e < EDGES; e += SCBLOCKS * 256) {
            int d = dst[e];
            int pos = g_ptr[d] + atomicAdd(&g_cursor[d], 1);
            g_csr_src[pos] = src[e];
        }
        return;
    }

    __shared__ __align__(16) float2 Ws2[CC * CC / 2];
    int tid = threadIdx.x;
    int tx = tid & 31, ty = tid >> 5;
    for (int i = tid; i < CC * CC / 2; i += 256)
        Ws2[i] = reinterpret_cast<const float2*>(W)[i];
    __syncthreads();

    int nt  = blockIdx.x % NTILES;
    int btt = blockIdx.x / NTILES;
    int n  = nt * 32 + tx;
    int bt = btt * 8 + ty;
    if (n >= NNODE) return;
    int b = bt / TT, t = bt - b * TT;

    const float* xp = x + ((size_t)b * CC * TT) * NNODE + (size_t)t * NNODE + n;
    float xa[CC];
    #pragma unroll
    for (int c = 0; c < CC; c++) xa[c] = __ldcs(xp + (size_t)c * TT * NNODE);

    unsigned long long acc2[16];
    #pragma unroll
    for (int j = 0; j < 16; j++) acc2[j] = 0ull;

    #pragma unroll
    for (int c = 0; c < CC; c++) {
        unsigned long long xv2;
        asm("mov.b64 %0, {%1, %1};" : "=l"(xv2) : "f"(xa[c]));
        const ulonglong2* wr =
            reinterpret_cast<const ulonglong2*>(Ws2 + c * (CC / 2));
        #pragma unroll
        for (int q = 0; q < 8; q++) {
            ulonglong2 w = wr[q];
            acc2[2*q]     = ffma2(xv2, w.x, acc2[2*q]);
            acc2[2*q + 1] = ffma2(xv2, w.y, acc2[2*q + 1]);
        }
    }

    float ns = g_norm_src[n];
    unsigned o32[16];
    #pragma unroll
    for (int j = 0; j < 16; j++) {
        float lo, hi;
        asm("mov.b64 {%0, %1}, %2;" : "=f"(lo), "=f"(hi) : "l"(acc2[j]));
        __half2 hh = __floats2half2_rn(lo * ns, hi * ns);
        o32[j] = *reinterpret_cast<unsigned*>(&hh);
    }
    uint4* yp = reinterpret_cast<uint4*>(g_y + (size_t)n * FF + (size_t)bt * CC);
    #pragma unroll
    for (int q = 0; q < 4; q++)
        yp[q] = make_uint4(o32[4*q], o32[4*q+1], o32[4*q+2], o32[4*q+3]);
}

// ---------------------------------------------------------------------------
// K4: persistent work-stealing aggregation. Groups of 4 edges (pad-to-4
// halves phantom-edge traffic vs pad-to-8: ~60MB saved on the binding
// L1/L2 path). fp16 HADD2 per group, fp32 upconvert per group.
// ---------------------------------------------------------------------------
__global__ __launch_bounds__(384)
void k_agg() {
    __shared__ int s_d;
    int tid = threadIdx.x;

    while (true) {
        if (tid == 0) s_d = atomicAdd(&g_work, 1);
        __syncthreads();
        int d = s_d;
        __syncthreads();
        if (d >= NNODE) return;

        if (tid == 0) {
            g_deg_in[d] = 0;
            g_deg_out[d] = 0;
            g_cursor[d] = 0;
        }

        int beg = g_ptr[d], end = g_ptr[d + 1];   // multiple of 4, 16B-aligned

        float2 acc[4];
        #pragma unroll
        for (int j = 0; j < 4; j++) acc[j] = make_float2(0.f, 0.f);

        for (int g0 = beg; g0 < end; g0 += 4) {
            int4 i0 = *reinterpret_cast<const int4*>(&g_csr_src[g0]);
            int idx[4] = { i0.x, i0.y, i0.z, i0.w };
            __half2 h[4];
            #pragma unroll
            for (int j = 0; j < 4; j++) h[j] = __floats2half2_rn(0.f, 0.f);
            #pragma unroll
            for (int k = 0; k < 4; k++) {
                const uint4* ys =
                    reinterpret_cast<const uint4*>(g_y + (size_t)idx[k] * FF);
                uint4 v = ys[tid];
                h[0] = __hadd2(h[0], *reinterpret_cast<const __half2*>(&v.x));
                h[1] = __hadd2(h[1], *reinterpret_cast<const __half2*>(&v.y));
                h[2] = __hadd2(h[2], *reinterpret_cast<const __half2*>(&v.z));
                h[3] = __hadd2(h[3], *reinterpret_cast<const __half2*>(&v.w));
            }
            #pragma unroll
            for (int j = 0; j < 4; j++) {
                float2 f = __half22float2(h[j]);
                acc[j].x += f.x; acc[j].y += f.y;
            }
        }

        float nd = g_norm_dst[d];
        __half2 o[4];
        #pragma unroll
        for (int j = 0; j < 4; j++)
            o[j] = __floats2half2_rn(acc[j].x * nd, acc[j].y * nd);
        uint4 pack;
        pack.x = *reinterpret_cast<unsigned*>(&o[0]);
        pack.y = *reinterpret_cast<unsigned*>(&o[1]);
        pack.z = *reinterpret_cast<unsigned*>(&o[2]);
        pack.w = *reinterpret_cast<unsigned*>(&o[3]);
        reinterpret_cast<uint4*>(g_agg + (size_t)d * FF)[tid] = pack;
    }
}

// ---------------------------------------------------------------------------
// K5: out[b,c,t,n] = relu(x[b,c,t,n] + bias[c] + agg[n][b][t][c])
// ---------------------------------------------------------------------------
#define ONODES 256
__global__ __launch_bounds__(512, 3)
void k_out(const float* __restrict__ x, const float* __restrict__ bias,
           float* __restrict__ out) {
    __shared__ float s[CC][ONODES + 4];
    int bt = blockIdx.y;
    int b = bt / TT, t = bt - b * TT;
    int n0 = blockIdx.x * ONODES;
    int tid = threadIdx.y * 64 + threadIdx.x;

    {
        int nl   = tid >> 1;
        int part = tid & 1;
        int n = n0 + nl;
        if (n < NNODE) {
            const uint4* ar =
                reinterpret_cast<const uint4*>(g_agg + (size_t)n * FF + (size_t)bt * CC);
            #pragma unroll
            for (int q = 0; q < 2; q++) {
                uint4 v = ar[part * 2 + q];
                int c0 = part * 16 + q * 8;
                const unsigned* u = &v.x;
                #pragma unroll
                for (int j = 0; j < 4; j++) {
                    float2 f = __half22float2(*reinterpret_cast<const __half2*>(&u[j]));
                    s[c0 + 2*j    ][nl] = f.x;
                    s[c0 + 2*j + 1][nl] = f.y;
                }
            }
        }
    }
    __syncthreads();

    int n4 = threadIdx.x * 4;
    int n = n0 + n4;
    if (n < NNODE) {
        #pragma unroll
        for (int k = 0; k < 4; k++) {
            int c = threadIdx.y + k * 8;
            float bc = bias[c];
            size_t idx = (((size_t)b * CC + c) * TT + t) * NNODE + n;
            float4 xv = __ldcs(reinterpret_cast<const float4*>(x + idx));
            float4 av = *reinterpret_cast<const float4*>(&s[c][n4]);
            float4 r;
            r.x = fmaxf(xv.x + bc + av.x, 0.f);
            r.y = fmaxf(xv.y + bc + av.y, 0.f);
            r.z = fmaxf(xv.z + bc + av.z, 0.f);
            r.w = fmaxf(xv.w + bc + av.w, 0.f);
            __stcs(reinterpret_cast<float4*>(out + idx), r);
        }
    }
}

// ---------------------------------------------------------------------------
// Launch: 5 kernels
// ---------------------------------------------------------------------------
extern "C" void kernel_launch(void* const* d_in, const int* in_sizes, int n_in,
                              void* d_out, int out_size) {
    const float* x    = (const float*)d_in[0];  // [B, C, T, N]
    const float* W    = (const float*)d_in[1];  // [C, C]
    const float* bias = (const float*)d_in[2];  // [C]
    const int*   src  = (const int*)d_in[3];    // [E]
    const int*   dst  = (const int*)d_in[4];    // [E]
    float*       out  = (float*)d_out;          // [B, C, T, N]

    k_deg<<<(EDGES + 255) / 256, 256>>>(src, dst);
    k_scan1b<<<1, 1024>>>();
    k_y_scatter<<<YBLOCKS + SCBLOCKS, 256>>>(x, W, src, dst);
    k_agg<<<AGGBLOCKS, 384>>>();
    k_out<<<dim3((NNODE + ONODES - 1) / ONODES, BT), dim3(64, 8)>>>(x, bias, out);
}

// round 11
// speedup vs baseline: 1.6457x; 1.0206x over previous
#include <cuda_runtime.h>
#include <cuda_fp16.h>
#include <cuda_bf16.h>

// Problem constants
#define BB 8
#define CC 32
#define TT 12
#define NNODE 5000
#define EDGES 80000
#define FF (BB*TT*CC)       // 3072 features per node
#define BT (BB*TT)          // 96
#define EPAD (EDGES + NNODE*3 + 8)  // padded CSR capacity (pad-to-4)

#define NTILES 157                  // ceil(5000/32)
#define YBLOCKS (NTILES * (BT/8))   // 157*12 = 1884 y-blocks
#define SCBLOCKS 40                 // scatter blocks appended to k_y grid
#define AGGBLOCKS 592               // persistent k_agg blocks (~4/SM)

// ---------------------------------------------------------------------------
// Scratch (static __device__ arrays — no allocations allowed).
// Counters zeroed after last use each call; first call relies on zero-init.
// ---------------------------------------------------------------------------
__device__ __align__(16) __half g_y  [(size_t)(NNODE + 1) * FF]; // +1 dummy zero node
__device__ __align__(16) __half g_agg[(size_t)NNODE * FF];
__device__ int    g_deg_in [NNODE];
__device__ int    g_deg_out[NNODE];
__device__ int    g_cursor [NNODE];
__device__ int    g_ptr    [NNODE + 1];          // padded CSR row ptr by dst
__device__ __align__(16) int g_csr_src[EPAD];    // src per edge (padded w/ NNODE)
__device__ float  g_norm_src[NNODE];
__device__ float  g_norm_dst[NNODE];
__device__ int    g_work;                        // k_agg work-stealing counter

// Packed 2xfp32 FMA (Blackwell FFMA2 — only reachable via PTX f32x2)
__device__ __forceinline__ unsigned long long ffma2(
    unsigned long long a, unsigned long long b, unsigned long long c) {
    unsigned long long d;
    asm("fma.rn.f32x2 %0, %1, %2, %3;" : "=l"(d) : "l"(a), "l"(b), "l"(c));
    return d;
}

// ---------------------------------------------------------------------------
// K1: degree histograms via distributed global atomics
// ---------------------------------------------------------------------------
__global__ void k_deg(const int* __restrict__ src, const int* __restrict__ dst) {
    int e = blockIdx.x * blockDim.x + threadIdx.x;
    if (e < EDGES) {
        atomicAdd(&g_deg_out[src[e]], 1);
        atomicAdd(&g_deg_in [dst[e]], 1);
    }
}

// ---------------------------------------------------------------------------
// K2: one block — norms, warp-shuffle exclusive scan of degrees padded to
// multiples of 4, pad-slot fill, dummy y row zero, work-counter reset.
// ---------------------------------------------------------------------------
__global__ __launch_bounds__(1024, 1)
void k_scan1b() {
    __shared__ int s_wsum[32];
    const int tid  = threadIdx.x;
    const int lane = tid & 31;
    const int warp = tid >> 5;

    if (tid == 0) g_work = 0;   // reset k_agg work counter for this replay

    for (int i = tid; i < NNODE; i += 1024) {
        g_norm_src[i] = rsqrtf((float)max(g_deg_out[i], 1));
        g_norm_dst[i] = rsqrtf((float)max(g_deg_in [i], 1));
    }

    const int base = tid * 5;
    int deg[5], pdeg[5];
    int tsum = 0;
    #pragma unroll
    for (int k = 0; k < 5; k++) {
        deg[k]  = (base + k < NNODE) ? g_deg_in[base + k] : 0;
        pdeg[k] = (deg[k] + 3) & ~3;
        tsum += pdeg[k];
    }
    int incl = tsum;
    #pragma unroll
    for (int off = 1; off < 32; off <<= 1) {
        int t = __shfl_up_sync(0xffffffffu, incl, off);
        if (lane >= off) incl += t;
    }
    if (lane == 31) s_wsum[warp] = incl;
    __syncthreads();
    if (warp == 0) {
        int w = s_wsum[lane];
        int wi = w;
        #pragma unroll
        for (int off = 1; off < 32; off <<= 1) {
            int t = __shfl_up_sync(0xffffffffu, wi, off);
            if (lane >= off) wi += t;
        }
        s_wsum[lane] = wi - w;
    }
    __syncthreads();

    int run = s_wsum[warp] + incl - tsum;
    #pragma unroll
    for (int k = 0; k < 5; k++) {
        int idx = base + k;
        if (idx < NNODE) {
            g_ptr[idx] = run;
            for (int j = deg[k]; j < pdeg[k]; j++) g_csr_src[run + j] = NNODE;
            run += pdeg[k];
        }
    }
    if (tid == (NNODE + 4) / 5 - 1) g_ptr[NNODE] = run;

    uint4 z = make_uint4(0, 0, 0, 0);
    uint4* dy = reinterpret_cast<uint4*>(g_y + (size_t)NNODE * FF);
    for (int i = tid; i < FF / 8; i += 1024) dy[i] = z;
}

// ---------------------------------------------------------------------------
// K3: fused y-GEMM + CSR scatter.
// y branch uses packed f32x2 FMA (FFMA2): c-outer loop, 16 packed
// accumulators, xv broadcast-packed once per c, W as ulonglong2 pairs from
// smem (LDS.128 broadcast). Halves FMA-pipe issue vs scalar FFMA.
// ---------------------------------------------------------------------------
__global__ __launch_bounds__(256)
void k_y_scatter(const float* __restrict__ x, const float* __restrict__ W,
                 const int* __restrict__ src, const int* __restrict__ dst) {
    if (blockIdx.x >= YBLOCKS) {
        int e0 = (blockIdx.x - YBLOCKS) * 256 + threadIdx.x;
        for (int e = e0; e < EDGES; e += SCBLOCKS * 256) {
            int d = dst[e];
            int pos = g_ptr[d] + atomicAdd(&g_cursor[d], 1);
            g_csr_src[pos] = src[e];
        }
        return;
    }

    __shared__ __align__(16) float2 Ws2[CC * CC / 2];
    int tid = threadIdx.x;
    int tx = tid & 31, ty = tid >> 5;
    for (int i = tid; i < CC * CC / 2; i += 256)
        Ws2[i] = reinterpret_cast<const float2*>(W)[i];
    __syncthreads();

    int nt  = blockIdx.x % NTILES;
    int btt = blockIdx.x / NTILES;
    int n  = nt * 32 + tx;
    int bt = btt * 8 + ty;
    if (n >= NNODE) return;
    int b = bt / TT, t = bt - b * TT;

    const float* xp = x + ((size_t)b * CC * TT) * NNODE + (size_t)t * NNODE + n;
    float xa[CC];
    #pragma unroll
    for (int c = 0; c < CC; c++) xa[c] = __ldcs(xp + (size_t)c * TT * NNODE);

    unsigned long long acc2[16];
    #pragma unroll
    for (int j = 0; j < 16; j++) acc2[j] = 0ull;

    #pragma unroll
    for (int c = 0; c < CC; c++) {
        unsigned long long xv2;
        asm("mov.b64 %0, {%1, %1};" : "=l"(xv2) : "f"(xa[c]));
        const ulonglong2* wr =
            reinterpret_cast<const ulonglong2*>(Ws2 + c * (CC / 2));
        #pragma unroll
        for (int q = 0; q < 8; q++) {
            ulonglong2 w = wr[q];
            acc2[2*q]     = ffma2(xv2, w.x, acc2[2*q]);
            acc2[2*q + 1] = ffma2(xv2, w.y, acc2[2*q + 1]);
        }
    }

    float ns = g_norm_src[n];
    unsigned o32[16];
    #pragma unroll
    for (int j = 0; j < 16; j++) {
        float lo, hi;
        asm("mov.b64 {%0, %1}, %2;" : "=f"(lo), "=f"(hi) : "l"(acc2[j]));
        __half2 hh = __floats2half2_rn(lo * ns, hi * ns);
        o32[j] = *reinterpret_cast<unsigned*>(&hh);
    }
    uint4* yp = reinterpret_cast<uint4*>(g_y + (size_t)n * FF + (size_t)bt * CC);
    #pragma unroll
    for (int q = 0; q < 4; q++)
        yp[q] = make_uint4(o32[4*q], o32[4*q+1], o32[4*q+2], o32[4*q+3]);
}

// ---------------------------------------------------------------------------
// K4: persistent work-stealing aggregation.
// Pad-to-4 traffic (minimal phantom edges) BUT 8-edge main loop for 8-deep
// per-thread MLP (R9's 4-deep loop dropped achieved L2 BW from 14.9 to
// 12.3 TB/s). Two independent 4-edge HADD2 chains per iteration (same fp16
// chain length as R9 -> same accuracy), fp32 upconvert per chain; single
// 4-edge tail when padded degree ≡ 4 (mod 8).
// ---------------------------------------------------------------------------
__global__ __launch_bounds__(384)
void k_agg() {
    __shared__ int s_d;
    int tid = threadIdx.x;

    while (true) {
        if (tid == 0) s_d = atomicAdd(&g_work, 1);
        __syncthreads();
        int d = s_d;
        __syncthreads();
        if (d >= NNODE) return;

        if (tid == 0) {
            g_deg_in[d] = 0;
            g_deg_out[d] = 0;
            g_cursor[d] = 0;
        }

        int beg = g_ptr[d], end = g_ptr[d + 1];   // multiple of 4, 16B-aligned

        float2 acc[4];
        #pragma unroll
        for (int j = 0; j < 4; j++) acc[j] = make_float2(0.f, 0.f);

        int g0 = beg;
        // main loop: 8 edges, two independent 4-edge chains (8 LDGs in flight)
        for (; g0 + 8 <= end; g0 += 8) {
            int4 i0 = *reinterpret_cast<const int4*>(&g_csr_src[g0]);
            int4 i1 = *reinterpret_cast<const int4*>(&g_csr_src[g0 + 4]);
            int idx[8] = { i0.x, i0.y, i0.z, i0.w, i1.x, i1.y, i1.z, i1.w };
            uint4 v[8];
            #pragma unroll
            for (int k = 0; k < 8; k++)
                v[k] = reinterpret_cast<const uint4*>(g_y + (size_t)idx[k] * FF)[tid];
            __half2 ha[4], hb[4];
            #pragma unroll
            for (int j = 0; j < 4; j++) {
                ha[j] = __hadd2(*reinterpret_cast<const __half2*>(&(&v[0].x)[j]),
                                *reinterpret_cast<const __half2*>(&(&v[1].x)[j]));
                hb[j] = __hadd2(*reinterpret_cast<const __half2*>(&(&v[4].x)[j]),
                                *reinterpret_cast<const __half2*>(&(&v[5].x)[j]));
            }
            #pragma unroll
            for (int j = 0; j < 4; j++) {
                ha[j] = __hadd2(ha[j], *reinterpret_cast<const __half2*>(&(&v[2].x)[j]));
                hb[j] = __hadd2(hb[j], *reinterpret_cast<const __half2*>(&(&v[6].x)[j]));
            }
            #pragma unroll
            for (int j = 0; j < 4; j++) {
                ha[j] = __hadd2(ha[j], *reinterpret_cast<const __half2*>(&(&v[3].x)[j]));
                hb[j] = __hadd2(hb[j], *reinterpret_cast<const __half2*>(&(&v[7].x)[j]));
            }
            #pragma unroll
            for (int j = 0; j < 4; j++) {
                float2 fa = __half22float2(ha[j]);
                float2 fb = __half22float2(hb[j]);
                acc[j].x += fa.x + fb.x;
                acc[j].y += fa.y + fb.y;
            }
        }
        // tail: one group of 4
        if (g0 < end) {
            int4 i0 = *reinterpret_cast<const int4*>(&g_csr_src[g0]);
            int idx[4] = { i0.x, i0.y, i0.z, i0.w };
            uint4 v[4];
            #pragma unroll
            for (int k = 0; k < 4; k++)
                v[k] = reinterpret_cast<const uint4*>(g_y + (size_t)idx[k] * FF)[tid];
            #pragma unroll
            for (int j = 0; j < 4; j++) {
                __half2 h =
                    __hadd2(__hadd2(*reinterpret_cast<const __half2*>(&(&v[0].x)[j]),
                                    *reinterpret_cast<const __half2*>(&(&v[1].x)[j])),
                            __hadd2(*reinterpret_cast<const __half2*>(&(&v[2].x)[j]),
                                    *reinterpret_cast<const __half2*>(&(&v[3].x)[j])));
                float2 f = __half22float2(h);
                acc[j].x += f.x; acc[j].y += f.y;
            }
        }

        float nd = g_norm_dst[d];
        __half2 o[4];
        #pragma unroll
        for (int j = 0; j < 4; j++)
            o[j] = __floats2half2_rn(acc[j].x * nd, acc[j].y * nd);
        uint4 pack;
        pack.x = *reinterpret_cast<unsigned*>(&o[0]);
        pack.y = *reinterpret_cast<unsigned*>(&o[1]);
        pack.z = *reinterpret_cast<unsigned*>(&o[2]);
        pack.w = *reinterpret_cast<unsigned*>(&o[3]);
        reinterpret_cast<uint4*>(g_agg + (size_t)d * FF)[tid] = pack;
    }
}

// ---------------------------------------------------------------------------
// K5: out[b,c,t,n] = relu(x[b,c,t,n] + bias[c] + agg[n][b][t][c])
// ---------------------------------------------------------------------------
#define ONODES 256
__global__ __launch_bounds__(512, 3)
void k_out(const float* __restrict__ x, const float* __restrict__ bias,
           float* __restrict__ out) {
    __shared__ float s[CC][ONODES + 4];
    int bt = blockIdx.y;
    int b = bt / TT, t = bt - b * TT;
    int n0 = blockIdx.x * ONODES;
    int tid = threadIdx.y * 64 + threadIdx.x;

    {
        int nl   = tid >> 1;
        int part = tid & 1;
        int n = n0 + nl;
        if (n < NNODE) {
            const uint4* ar =
                reinterpret_cast<const uint4*>(g_agg + (size_t)n * FF + (size_t)bt * CC);
            #pragma unroll
            for (int q = 0; q < 2; q++) {
                uint4 v = ar[part * 2 + q];
                int c0 = part * 16 + q * 8;
                const unsigned* u = &v.x;
                #pragma unroll
                for (int j = 0; j < 4; j++) {
                    float2 f = __half22float2(*reinterpret_cast<const __half2*>(&u[j]));
                    s[c0 + 2*j    ][nl] = f.x;
                    s[c0 + 2*j + 1][nl] = f.y;
                }
            }
        }
    }
    __syncthreads();

    int n4 = threadIdx.x * 4;
    int n = n0 + n4;
    if (n < NNODE) {
        #pragma unroll
        for (int k = 0; k < 4; k++) {
            int c = threadIdx.y + k * 8;
            float bc = bias[c];
            size_t idx = (((size_t)b * CC + c) * TT + t) * NNODE + n;
            float4 xv = __ldcs(reinterpret_cast<const float4*>(x + idx));
            float4 av = *reinterpret_cast<const float4*>(&s[c][n4]);
            float4 r;
            r.x = fmaxf(xv.x + bc + av.x, 0.f);
            r.y = fmaxf(xv.y + bc + av.y, 0.f);
            r.z = fmaxf(xv.z + bc + av.z, 0.f);
            r.w = fmaxf(xv.w + bc + av.w, 0.f);
            __stcs(reinterpret_cast<float4*>(out + idx), r);
        }
    }
}

// ---------------------------------------------------------------------------
// Launch: 5 kernels
// ---------------------------------------------------------------------------
extern "C" void kernel_launch(void* const* d_in, const int* in_sizes, int n_in,
                              void* d_out, int out_size) {
    const float* x    = (const float*)d_in[0];  // [B, C, T, N]
    const float* W    = (const float*)d_in[1];  // [C, C]
    const float* bias = (const float*)d_in[2];  // [C]
    const int*   src  = (const int*)d_in[3];    // [E]
    const int*   dst  = (const int*)d_in[4];    // [E]
    float*       out  = (float*)d_out;          // [B, C, T, N]

    k_deg<<<(EDGES + 255) / 256, 256>>>(src, dst);
    k_scan1b<<<1, 1024>>>();
    k_y_scatter<<<YBLOCKS + SCBLOCKS, 256>>>(x, W, src, dst);
    k_agg<<<AGGBLOCKS, 384>>>();
    k_out<<<dim3((NNODE + ONODES - 1) / ONODES, BT), dim3(64, 8)>>>(x, bias, out);
}

// round 12
// speedup vs baseline: 1.6967x; 1.0310x over previous
#include <cuda_runtime.h>
#include <cuda_fp16.h>
#include <cuda_bf16.h>

// Problem constants
#define BB 8
#define CC 32
#define TT 12
#define NNODE 5000
#define EDGES 80000
#define FF (BB*TT*CC)       // 3072 features per node
#define BT (BB*TT)          // 96
#define EPAD (EDGES + NNODE*3 + 8)  // padded CSR capacity (pad-to-4)

#define NTILES 157                  // ceil(5000/32)
#define YBLOCKS (NTILES * (BT/8))   // 157*12 = 1884 y-blocks
#define PREPB 120                   // resident prep blocks (phase-barriered)
#define AGGBLOCKS 592               // persistent k_agg blocks (~4/SM)

// ---------------------------------------------------------------------------
// Scratch (static __device__ arrays — no allocations allowed).
// Counters zeroed after last use each call; first call relies on zero-init.
// g_y row NNODE (dummy) is NEVER written -> stays zero from static init.
// ---------------------------------------------------------------------------
__device__ __align__(16) __half g_y  [(size_t)(NNODE + 1) * FF]; // +1 dummy zero row
__device__ __align__(16) __half g_agg[(size_t)NNODE * FF];
__device__ int    g_deg_in [NNODE];
__device__ int    g_deg_out[NNODE];
__device__ int    g_cursor [NNODE];
__device__ int    g_ptr    [NNODE + 1];          // padded CSR row ptr by dst
__device__ __align__(16) unsigned g_csr[EPAD];   // (fp16 ns_src << 16) | src
__device__ float  g_norm_src[NNODE];
__device__ float  g_norm_dst[NNODE];
__device__ int    g_work;                        // k_agg work-stealing counter
__device__ int    g_bar_cnt;                     // prep phase barrier counter

// Packed 2xfp32 FMA (Blackwell FFMA2 — only reachable via PTX f32x2)
__device__ __forceinline__ unsigned long long ffma2(
    unsigned long long a, unsigned long long b, unsigned long long c) {
    unsigned long long d;
    asm("fma.rn.f32x2 %0, %1, %2, %3;" : "=l"(d) : "l"(a), "l"(b), "l"(c));
    return d;
}

// Phase barrier for the PREPB resident blocks. Not a deadlock risk: y-blocks
// never wait, so a late prep block only delays the chain, never hangs it.
__device__ __forceinline__ void prep_bar(int target) {
    __syncthreads();
    if (threadIdx.x == 0) {
        __threadfence();
        atomicAdd(&g_bar_cnt, 1);
        while (atomicAdd(&g_bar_cnt, 0) < target) __nanosleep(64);
    }
    __syncthreads();
}

// build half2(ns, ns) from packed CSR word (ns fp16 bits in [31:16])
__device__ __forceinline__ __half2 mkns2(unsigned u) {
    unsigned r = (u & 0xFFFF0000u) | (u >> 16);
    return *reinterpret_cast<__half2*>(&r);
}

// ---------------------------------------------------------------------------
// K1: ONE kernel = prep chain (120 barriered blocks) + y'-GEMM (1884 blocks).
// Prep: phase A degree histograms -> barrier -> phase B (block 0: norms,
// padded exclusive scan -> g_ptr, g_work reset) -> barrier -> phase C
// scatter with fp16-ns packing + pad fill.
// y' = xW (UNNORMALIZED -> zero dependency on prep; norm_src applied in
// k_agg via HFMA2 with the packed ns). FFMA2 path as in R10.
// ---------------------------------------------------------------------------
__global__ __launch_bounds__(256)
void k_prep_y(const float* __restrict__ x, const float* __restrict__ W,
              const int* __restrict__ src, const int* __restrict__ dst) {
    if (blockIdx.x < PREPB) {
        // ================= prep branch =================
        const int tid  = threadIdx.x;
        const int gtid = blockIdx.x * 256 + tid;

        // phase A: degree histograms (distributed global atomics)
        for (int e = gtid; e < EDGES; e += PREPB * 256) {
            atomicAdd(&g_deg_out[src[e]], 1);
            atomicAdd(&g_deg_in [dst[e]], 1);
        }
        prep_bar(PREPB);

        // phase B: block 0 only — norms + padded exclusive scan
        if (blockIdx.x == 0) {
            __shared__ int s_wsum[8];
            const int lane = tid & 31;
            const int warp = tid >> 5;

            if (tid == 0) g_work = 0;

            for (int i = tid; i < NNODE; i += 256) {
                g_norm_src[i] = rsqrtf((float)max(g_deg_out[i], 1));
                g_norm_dst[i] = rsqrtf((float)max(g_deg_in [i], 1));
            }

            // scan of pad-4 degrees: 20 nodes/thread (256*20 = 5120)
            const int base = tid * 20;
            int pd[20];
            int tsum = 0;
            #pragma unroll
            for (int k = 0; k < 20; k++) {
                int dg = (base + k < NNODE) ? g_deg_in[base + k] : 0;
                pd[k] = (dg + 3) & ~3;
                tsum += pd[k];
            }
            int incl = tsum;
            #pragma unroll
            for (int off = 1; off < 32; off <<= 1) {
                int t = __shfl_up_sync(0xffffffffu, incl, off);
                if (lane >= off) incl += t;
            }
            if (lane == 31) s_wsum[warp] = incl;
            __syncthreads();
            if (tid == 0) {
                int r = 0;
                #pragma unroll
                for (int w = 0; w < 8; w++) { int t = s_wsum[w]; s_wsum[w] = r; r += t; }
            }
            __syncthreads();

            int run = s_wsum[warp] + incl - tsum;
            #pragma unroll
            for (int k = 0; k < 20; k++) {
                int idx = base + k;
                if (idx < NNODE) { g_ptr[idx] = run; run += pd[k]; }
            }
            if (tid == (NNODE + 19) / 20 - 1) g_ptr[NNODE] = run;
        }
        prep_bar(2 * PREPB);

        // phase C: scatter (pack fp16 norm_src into bits [31:16]) + pad fill
        for (int e = gtid; e < EDGES; e += PREPB * 256) {
            int s = src[e], d = dst[e];
            int pos = __ldcg(&g_ptr[d]) + atomicAdd(&g_cursor[d], 1);
            unsigned nsb = (unsigned)__half_as_ushort(
                               __float2half_rn(__ldcg(&g_norm_src[s])));
            g_csr[pos] = (unsigned)s | (nsb << 16);
        }
        for (int i = gtid; i < NNODE; i += PREPB * 256) {
            int p  = __ldcg(&g_ptr[i]);
            int dg = __ldcg(&g_deg_in[i]);
            int pad = (dg + 3) & ~3;
            for (int j = dg; j < pad; j++) g_csr[p + j] = NNODE;  // ns=0, zero row
        }
        return;
    }

    // ================= y' branch (no prep dependency) =================
    __shared__ __align__(16) float2 Ws2[CC * CC / 2];
    int tid = threadIdx.x;
    int tx = tid & 31, ty = tid >> 5;
    for (int i = tid; i < CC * CC / 2; i += 256)
        Ws2[i] = reinterpret_cast<const float2*>(W)[i];
    __syncthreads();

    int yb  = blockIdx.x - PREPB;
    int nt  = yb % NTILES;
    int btt = yb / NTILES;
    int n  = nt * 32 + tx;
    int bt = btt * 8 + ty;
    if (n >= NNODE) return;
    int b = bt / TT, t = bt - b * TT;

    const float* xp = x + ((size_t)b * CC * TT) * NNODE + (size_t)t * NNODE + n;
    float xa[CC];
    #pragma unroll
    for (int c = 0; c < CC; c++) xa[c] = __ldcs(xp + (size_t)c * TT * NNODE);

    unsigned long long acc2[16];
    #pragma unroll
    for (int j = 0; j < 16; j++) acc2[j] = 0ull;

    #pragma unroll
    for (int c = 0; c < CC; c++) {
        unsigned long long xv2;
        asm("mov.b64 %0, {%1, %1};" : "=l"(xv2) : "f"(xa[c]));
        const ulonglong2* wr =
            reinterpret_cast<const ulonglong2*>(Ws2 + c * (CC / 2));
        #pragma unroll
        for (int q = 0; q < 8; q++) {
            ulonglong2 w = wr[q];
            acc2[2*q]     = ffma2(xv2, w.x, acc2[2*q]);
            acc2[2*q + 1] = ffma2(xv2, w.y, acc2[2*q + 1]);
        }
    }

    unsigned o32[16];
    #pragma unroll
    for (int j = 0; j < 16; j++) {
        float lo, hi;
        asm("mov.b64 {%0, %1}, %2;" : "=f"(lo), "=f"(hi) : "l"(acc2[j]));
        __half2 hh = __floats2half2_rn(lo, hi);   // unnormalized
        o32[j] = *reinterpret_cast<unsigned*>(&hh);
    }
    uint4* yp = reinterpret_cast<uint4*>(g_y + (size_t)n * FF + (size_t)bt * CC);
    #pragma unroll
    for (int q = 0; q < 4; q++)
        yp[q] = make_uint4(o32[4*q], o32[4*q+1], o32[4*q+2], o32[4*q+3]);
}

// ---------------------------------------------------------------------------
// K2: persistent work-stealing aggregation.
// agg[d] = norm_dst[d] * sum_e ns_src(e) * y'[src(e)]
// 8-edge main loop (8-deep MLP), two independent 4-edge HFMA2 chains with
// per-edge ns from the packed CSR word (2 ALU ops, no load). fp32 upconvert
// per chain; 4-edge tail. Zeroes counters + barrier counter for next replay.
// ---------------------------------------------------------------------------
__global__ __launch_bounds__(384)
void k_agg() {
    __shared__ int s_d;
    int tid = threadIdx.x;
    if (blockIdx.x == 0 && tid == 0) g_bar_cnt = 0;   // reset prep barrier

    while (true) {
        if (tid == 0) s_d = atomicAdd(&g_work, 1);
        __syncthreads();
        int d = s_d;
        __syncthreads();
        if (d >= NNODE) return;

        if (tid == 0) {
            g_deg_in[d] = 0;
            g_deg_out[d] = 0;
            g_cursor[d] = 0;
        }

        int beg = g_ptr[d], end = g_ptr[d + 1];   // multiple of 4, 16B-aligned

        float2 acc[4];
        #pragma unroll
        for (int j = 0; j < 4; j++) acc[j] = make_float2(0.f, 0.f);

        int g0 = beg;
        for (; g0 + 8 <= end; g0 += 8) {
            uint4 i0 = *reinterpret_cast<const uint4*>(&g_csr[g0]);
            uint4 i1 = *reinterpret_cast<const uint4*>(&g_csr[g0 + 4]);
            unsigned u[8] = { i0.x, i0.y, i0.z, i0.w, i1.x, i1.y, i1.z, i1.w };
            uint4 v[8];
            #pragma unroll
            for (int k = 0; k < 8; k++)
                v[k] = reinterpret_cast<const uint4*>(
                           g_y + (size_t)(u[k] & 0xFFFFu) * FF)[tid];
            __half2 ha[4], hb[4];
            #pragma unroll
            for (int j = 0; j < 4; j++) {
                ha[j] = __floats2half2_rn(0.f, 0.f);
                hb[j] = __floats2half2_rn(0.f, 0.f);
            }
            #pragma unroll
            for (int k = 0; k < 4; k++) {
                __half2 nA = mkns2(u[k]);
                __half2 nB = mkns2(u[k + 4]);
                #pragma unroll
                for (int j = 0; j < 4; j++) {
                    ha[j] = __hfma2(*reinterpret_cast<const __half2*>(&(&v[k].x)[j]),
                                    nA, ha[j]);
                    hb[j] = __hfma2(*reinterpret_cast<const __half2*>(&(&v[k+4].x)[j]),
                                    nB, hb[j]);
                }
            }
            #pragma unroll
            for (int j = 0; j < 4; j++) {
                float2 fa = __half22float2(ha[j]);
                float2 fb = __half22float2(hb[j]);
                acc[j].x += fa.x + fb.x;
                acc[j].y += fa.y + fb.y;
            }
        }
        if (g0 < end) {            // tail: one group of 4
            uint4 i0 = *reinterpret_cast<const uint4*>(&g_csr[g0]);
            unsigned u[4] = { i0.x, i0.y, i0.z, i0.w };
            uint4 v[4];
            #pragma unroll
            for (int k = 0; k < 4; k++)
                v[k] = reinterpret_cast<const uint4*>(
                           g_y + (size_t)(u[k] & 0xFFFFu) * FF)[tid];
            #pragma unroll
            for (int j = 0; j < 4; j++) {
                __half2 h = __floats2half2_rn(0.f, 0.f);
                #pragma unroll
                for (int k = 0; k < 4; k++)
                    h = __hfma2(*reinterpret_cast<const __half2*>(&(&v[k].x)[j]),
                                mkns2(u[k]), h);
                float2 f = __half22float2(h);
                acc[j].x += f.x; acc[j].y += f.y;
            }
        }

        float nd = g_norm_dst[d];
        __half2 o[4];
        #pragma unroll
        for (int j = 0; j < 4; j++)
            o[j] = __floats2half2_rn(acc[j].x * nd, acc[j].y * nd);
        uint4 pack;
        pack.x = *reinterpret_cast<unsigned*>(&o[0]);
        pack.y = *reinterpret_cast<unsigned*>(&o[1]);
        pack.z = *reinterpret_cast<unsigned*>(&o[2]);
        pack.w = *reinterpret_cast<unsigned*>(&o[3]);
        reinterpret_cast<uint4*>(g_agg + (size_t)d * FF)[tid] = pack;
    }
}

// ---------------------------------------------------------------------------
// K3: out[b,c,t,n] = relu(x[b,c,t,n] + bias[c] + agg[n][b][t][c])
// ---------------------------------------------------------------------------
#define ONODES 256
__global__ __launch_bounds__(512, 3)
void k_out(const float* __restrict__ x, const float* __restrict__ bias,
           float* __restrict__ out) {
    __shared__ float s[CC][ONODES + 4];
    int bt = blockIdx.y;
    int b = bt / TT, t = bt - b * TT;
    int n0 = blockIdx.x * ONODES;
    int tid = threadIdx.y * 64 + threadIdx.x;

    {
        int nl   = tid >> 1;
        int part = tid & 1;
        int n = n0 + nl;
        if (n < NNODE) {
            const uint4* ar =
                reinterpret_cast<const uint4*>(g_agg + (size_t)n * FF + (size_t)bt * CC);
            #pragma unroll
            for (int q = 0; q < 2; q++) {
                uint4 v = ar[part * 2 + q];
                int c0 = part * 16 + q * 8;
                const unsigned* u = &v.x;
                #pragma unroll
                for (int j = 0; j < 4; j++) {
                    float2 f = __half22float2(*reinterpret_cast<const __half2*>(&u[j]));
                    s[c0 + 2*j    ][nl] = f.x;
                    s[c0 + 2*j + 1][nl] = f.y;
                }
            }
        }
    }
    __syncthreads();

    int n4 = threadIdx.x * 4;
    int n = n0 + n4;
    if (n < NNODE) {
        #pragma unroll
        for (int k = 0; k < 4; k++) {
            int c = threadIdx.y + k * 8;
            float bc = bias[c];
            size_t idx = (((size_t)b * CC + c) * TT + t) * NNODE + n;
            float4 xv = __ldcs(reinterpret_cast<const float4*>(x + idx));
            float4 av = *reinterpret_cast<const float4*>(&s[c][n4]);
            float4 r;
            r.x = fmaxf(xv.x + bc + av.x, 0.f);
            r.y = fmaxf(xv.y + bc + av.y, 0.f);
            r.z = fmaxf(xv.z + bc + av.z, 0.f);
            r.w = fmaxf(xv.w + bc + av.w, 0.f);
            __stcs(reinterpret_cast<float4*>(out + idx), r);
        }
    }
}

// ---------------------------------------------------------------------------
// Launch: 3 kernels (was 5)
// ---------------------------------------------------------------------------
extern "C" void kernel_launch(void* const* d_in, const int* in_sizes, int n_in,
                              void* d_out, int out_size) {
    const float* x    = (const float*)d_in[0];  // [B, C, T, N]
    const float* W    = (const float*)d_in[1];  // [C, C]
    const float* bias = (const float*)d_in[2];  // [C]
    const int*   src  = (const int*)d_in[3];    // [E]
    const int*   dst  = (const int*)d_in[4];    // [E]
    float*       out  = (float*)d_out;          // [B, C, T, N]

    k_prep_y<<<PREPB + YBLOCKS, 256>>>(x, W, src, dst);
    k_agg<<<AGGBLOCKS, 384>>>();
    k_out<<<dim3((NNODE + ONODES - 1) / ONODES, BT), dim3(64, 8)>>>(x, bias, out);
}

// round 14
// speedup vs baseline: 1.7241x; 1.0162x over previous
#include <cuda_runtime.h>
#include <cuda_fp16.h>
#include <cuda_bf16.h>

// Problem constants
#define BB 8
#define CC 32
#define TT 12
#define NNODE 5000
#define EDGES 80000
#define FF (BB*TT*CC)       // 3072 features per node
#define BT (BB*TT)          // 96
#define EPAD (EDGES + NNODE*3 + 8)  // padded CSR capacity (pad-to-4)

#define NTILES 157                  // ceil(5000/32)
#define YBLOCKS (NTILES * (BT/8))   // 157*12 = 1884 y-blocks
#define PREPB 120                   // resident prep blocks (phase-barriered)
#define AGGBLOCKS 592               // persistent k_agg blocks (~4/SM)

// ---------------------------------------------------------------------------
// Scratch (static __device__ arrays — no allocations allowed).
// Counters zeroed after last use each call; first call relies on zero-init.
// g_y row NNODE (dummy) is NEVER written -> stays zero from static init.
// ---------------------------------------------------------------------------
__device__ __align__(16) __half g_y  [(size_t)(NNODE + 1) * FF]; // +1 dummy zero row
__device__ __align__(16) __half g_agg[(size_t)NNODE * FF];
__device__ int    g_deg_in [NNODE];
__device__ int    g_deg_out[NNODE];
__device__ int    g_cursor [NNODE];
__device__ int    g_ptr    [NNODE + 1];          // padded CSR row ptr by dst
__device__ __align__(16) unsigned g_csr[EPAD];   // (fp16 ns_src << 16) | src
__device__ float  g_norm_src[NNODE];
__device__ float  g_norm_dst[NNODE];
__device__ int    g_work;                        // k_agg work-stealing counter
__device__ int    g_bar_cnt;                     // prep phase barrier counter

// Packed 2xfp32 FMA (Blackwell FFMA2 — only reachable via PTX f32x2)
__device__ __forceinline__ unsigned long long ffma2(
    unsigned long long a, unsigned long long b, unsigned long long c) {
    unsigned long long d;
    asm("fma.rn.f32x2 %0, %1, %2, %3;" : "=l"(d) : "l"(a), "l"(b), "l"(c));
    return d;
}

// Phase barrier for the PREPB resident blocks. Not a deadlock risk: prep
// blocks are blockIdx 0..119 (all wave-1 resident), y-blocks never wait.
__device__ __forceinline__ void prep_bar(int target) {
    __syncthreads();
    if (threadIdx.x == 0) {
        __threadfence();
        atomicAdd(&g_bar_cnt, 1);
        while (atomicAdd(&g_bar_cnt, 0) < target) __nanosleep(64);
    }
    __syncthreads();
}

// build half2(ns, ns) from packed CSR word (ns fp16 bits in [31:16])
__device__ __forceinline__ __half2 mkns2(unsigned u) {
    unsigned r = (u & 0xFFFF0000u) | (u >> 16);
    return *reinterpret_cast<__half2*>(&r);
}

// ---------------------------------------------------------------------------
// K1: ONE kernel = prep chain (120 barriered blocks) + y'-GEMM (1884 blocks).
// Prep: phase A degree histograms -> barrier -> phase B (block 0: norms,
// padded exclusive scan -> g_ptr, g_work reset) -> barrier -> phase C
// scatter with fp16-ns packing + pad fill.
// y' = xW (UNNORMALIZED -> zero dependency on prep; norm_src applied in
// k_agg via HFMA2 with the packed ns).
// y branch register-restructured: xa[32] -> pipelined 4-elem double buffer,
// launch_bounds(256,4) -> 32 warps/SM (was 24 at 76 regs).
// ---------------------------------------------------------------------------
__global__ __launch_bounds__(256, 4)
void k_prep_y(const float* __restrict__ x, const float* __restrict__ W,
              const int* __restrict__ src, const int* __restrict__ dst) {
    if (blockIdx.x < PREPB) {
        // ================= prep branch =================
        const int tid  = threadIdx.x;
        const int gtid = blockIdx.x * 256 + tid;

        // phase A: degree histograms (distributed global atomics)
        for (int e = gtid; e < EDGES; e += PREPB * 256) {
            atomicAdd(&g_deg_out[src[e]], 1);
            atomicAdd(&g_deg_in [dst[e]], 1);
        }
        prep_bar(PREPB);

        // phase B: block 0 only — norms + padded exclusive scan
        if (blockIdx.x == 0) {
            __shared__ int s_wsum[8];
            const int lane = tid & 31;
            const int warp = tid >> 5;

            if (tid == 0) g_work = 0;

            for (int i = tid; i < NNODE; i += 256) {
                g_norm_src[i] = rsqrtf((float)max(g_deg_out[i], 1));
                g_norm_dst[i] = rsqrtf((float)max(g_deg_in [i], 1));
            }

            // scan of pad-4 degrees: 20 nodes/thread (256*20 = 5120)
            const int base = tid * 20;
            int pd[20];
            int tsum = 0;
            #pragma unroll
            for (int k = 0; k < 20; k++) {
                int dg = (base + k < NNODE) ? g_deg_in[base + k] : 0;
                pd[k] = (dg + 3) & ~3;
                tsum += pd[k];
            }
            int incl = tsum;
            #pragma unroll
            for (int off = 1; off < 32; off <<= 1) {
                int t = __shfl_up_sync(0xffffffffu, incl, off);
                if (lane >= off) incl += t;
            }
            if (lane == 31) s_wsum[warp] = incl;
            __syncthreads();
            if (tid == 0) {
                int r = 0;
                #pragma unroll
                for (int w = 0; w < 8; w++) { int t = s_wsum[w]; s_wsum[w] = r; r += t; }
            }
            __syncthreads();

            int run = s_wsum[warp] + incl - tsum;
            #pragma unroll
            for (int k = 0; k < 20; k++) {
                int idx = base + k;
                if (idx < NNODE) { g_ptr[idx] = run; run += pd[k]; }
            }
            if (tid == (NNODE + 19) / 20 - 1) g_ptr[NNODE] = run;
        }
        prep_bar(2 * PREPB);

        // phase C: scatter (pack fp16 norm_src into bits [31:16]) + pad fill
        for (int e = gtid; e < EDGES; e += PREPB * 256) {
            int s = src[e], d = dst[e];
            int pos = __ldcg(&g_ptr[d]) + atomicAdd(&g_cursor[d], 1);
            unsigned nsb = (unsigned)__half_as_ushort(
                               __float2half_rn(__ldcg(&g_norm_src[s])));
            g_csr[pos] = (unsigned)s | (nsb << 16);
        }
        for (int i = gtid; i < NNODE; i += PREPB * 256) {
            int p  = __ldcg(&g_ptr[i]);
            int dg = __ldcg(&g_deg_in[i]);
            int pad = (dg + 3) & ~3;
            for (int j = dg; j < pad; j++) g_csr[p + j] = NNODE;  // ns=0, zero row
        }
        return;
    }

    // ================= y' branch (no prep dependency) =================
    __shared__ __align__(16) float2 Ws2[CC * CC / 2];
    int tid = threadIdx.x;
    int tx = tid & 31, ty = tid >> 5;
    for (int i = tid; i < CC * CC / 2; i += 256)
        Ws2[i] = reinterpret_cast<const float2*>(W)[i];
    __syncthreads();

    int yb  = blockIdx.x - PREPB;
    int nt  = yb % NTILES;
    int btt = yb / NTILES;
    int n  = nt * 32 + tx;
    int bt = btt * 8 + ty;
    if (n >= NNODE) return;
    int b = bt / TT, t = bt - b * TT;

    const float* xp = x + ((size_t)b * CC * TT) * NNODE + (size_t)t * NNODE + n;
    const size_t cstride = (size_t)TT * NNODE;

    unsigned long long acc2[16];
    #pragma unroll
    for (int j = 0; j < 16; j++) acc2[j] = 0ull;

    // software-pipelined c-loop: 8 chunks of 4, double-buffered x loads
    float xa_cur[4], xa_nxt[4];
    #pragma unroll
    for (int k = 0; k < 4; k++) {
        xa_cur[k] = __ldcs(xp + (size_t)k * cstride);
        xa_nxt[k] = 0.0f;   // defined value for the final (discarded) rotate
    }

    #pragma unroll
    for (int ch = 0; ch < 8; ch++) {
        if (ch < 7) {
            #pragma unroll
            for (int k = 0; k < 4; k++)
                xa_nxt[k] = __ldcs(xp + (size_t)(ch * 4 + 4 + k) * cstride);
        }
        #pragma unroll
        for (int kc = 0; kc < 4; kc++) {
            int c = ch * 4 + kc;
            unsigned long long xv2;
            asm("mov.b64 %0, {%1, %1};" : "=l"(xv2) : "f"(xa_cur[kc]));
            const ulonglong2* wr =
                reinterpret_cast<const ulonglong2*>(Ws2 + c * (CC / 2));
            #pragma unroll
            for (int q = 0; q < 8; q++) {
                ulonglong2 w = wr[q];
                acc2[2*q]     = ffma2(xv2, w.x, acc2[2*q]);
                acc2[2*q + 1] = ffma2(xv2, w.y, acc2[2*q + 1]);
            }
        }
        #pragma unroll
        for (int k = 0; k < 4; k++) xa_cur[k] = xa_nxt[k];
    }

    unsigned o32[16];
    #pragma unroll
    for (int j = 0; j < 16; j++) {
        float lo, hi;
        asm("mov.b64 {%0, %1}, %2;" : "=f"(lo), "=f"(hi) : "l"(acc2[j]));
        __half2 hh = __floats2half2_rn(lo, hi);   // unnormalized
        o32[j] = *reinterpret_cast<unsigned*>(&hh);
    }
    uint4* yp = reinterpret_cast<uint4*>(g_y + (size_t)n * FF + (size_t)bt * CC);
    #pragma unroll
    for (int q = 0; q < 4; q++)
        yp[q] = make_uint4(o32[4*q], o32[4*q+1], o32[4*q+2], o32[4*q+3]);
}

// ---------------------------------------------------------------------------
// K2: persistent work-stealing aggregation.
// agg[d] = norm_dst[d] * sum_e ns_src(e) * y'[src(e)]
// 8-edge main loop (8-deep MLP), two independent 4-edge HFMA2 chains with
// per-edge ns from the packed CSR word. fp32 upconvert per chain; 4-edge
// tail. Zeroes counters + barrier counter for next replay.
// ---------------------------------------------------------------------------
__global__ __launch_bounds__(384)
void k_agg() {
    __shared__ int s_d;
    int tid = threadIdx.x;
    if (blockIdx.x == 0 && tid == 0) g_bar_cnt = 0;   // reset prep barrier

    while (true) {
        if (tid == 0) s_d = atomicAdd(&g_work, 1);
        __syncthreads();
        int d = s_d;
        __syncthreads();
        if (d >= NNODE) return;

        if (tid == 0) {
            g_deg_in[d] = 0;
            g_deg_out[d] = 0;
            g_cursor[d] = 0;
        }

        int beg = g_ptr[d], end = g_ptr[d + 1];   // multiple of 4, 16B-aligned

        float2 acc[4];
        #pragma unroll
        for (int j = 0; j < 4; j++) acc[j] = make_float2(0.f, 0.f);

        int g0 = beg;
        for (; g0 + 8 <= end; g0 += 8) {
            uint4 i0 = *reinterpret_cast<const uint4*>(&g_csr[g0]);
            uint4 i1 = *reinterpret_cast<const uint4*>(&g_csr[g0 + 4]);
            unsigned u[8] = { i0.x, i0.y, i0.z, i0.w, i1.x, i1.y, i1.z, i1.w };
            uint4 v[8];
            #pragma unroll
            for (int k = 0; k < 8; k++)
                v[k] = reinterpret_cast<const uint4*>(
                           g_y + (size_t)(u[k] & 0xFFFFu) * FF)[tid];
            __half2 ha[4], hb[4];
            #pragma unroll
            for (int j = 0; j < 4; j++) {
                ha[j] = __floats2half2_rn(0.f, 0.f);
                hb[j] = __floats2half2_rn(0.f, 0.f);
            }
            #pragma unroll
            for (int k = 0; k < 4; k++) {
                __half2 nA = mkns2(u[k]);
                __half2 nB = mkns2(u[k + 4]);
                #pragma unroll
                for (int j = 0; j < 4; j++) {
                    ha[j] = __hfma2(*reinterpret_cast<const __half2*>(&(&v[k].x)[j]),
                                    nA, ha[j]);
                    hb[j] = __hfma2(*reinterpret_cast<const __half2*>(&(&v[k+4].x)[j]),
                                    nB, hb[j]);
                }
            }
            #pragma unroll
            for (int j = 0; j < 4; j++) {
                float2 fa = __half22float2(ha[j]);
                float2 fb = __half22float2(hb[j]);
                acc[j].x += fa.x + fb.x;
                acc[j].y += fa.y + fb.y;
            }
        }
        if (g0 < end) {            // tail: one group of 4
            uint4 i0 = *reinterpret_cast<const uint4*>(&g_csr[g0]);
            unsigned u[4] = { i0.x, i0.y, i0.z, i0.w };
            uint4 v[4];
            #pragma unroll
            for (int k = 0; k < 4; k++)
                v[k] = reinterpret_cast<const uint4*>(
                           g_y + (size_t)(u[k] & 0xFFFFu) * FF)[tid];
            #pragma unroll
            for (int j = 0; j < 4; j++) {
                __half2 h = __floats2half2_rn(0.f, 0.f);
                #pragma unroll
                for (int k = 0; k < 4; k++)
                    h = __hfma2(*reinterpret_cast<const __half2*>(&(&v[k].x)[j]),
                                mkns2(u[k]), h);
                float2 f = __half22float2(h);
                acc[j].x += f.x; acc[j].y += f.y;
            }
        }

        float nd = g_norm_dst[d];
        __half2 o[4];
        #pragma unroll
        for (int j = 0; j < 4; j++)
            o[j] = __floats2half2_rn(acc[j].x * nd, acc[j].y * nd);
        uint4 pack;
        pack.x = *reinterpret_cast<unsigned*>(&o[0]);
        pack.y = *reinterpret_cast<unsigned*>(&o[1]);
        pack.z = *reinterpret_cast<unsigned*>(&o[2]);
        pack.w = *reinterpret_cast<unsigned*>(&o[3]);
        reinterpret_cast<uint4*>(g_agg + (size_t)d * FF)[tid] = pack;
    }
}

// ---------------------------------------------------------------------------
// K3: out[b,c,t,n] = relu(x[b,c,t,n] + bias[c] + agg[n][b][t][c])
// ---------------------------------------------------------------------------
#define ONODES 256
__global__ __launch_bounds__(512, 3)
void k_out(const float* __restrict__ x, const float* __restrict__ bias,
           float* __restrict__ out) {
    __shared__ float s[CC][ONODES + 4];
    int bt = blockIdx.y;
    int b = bt / TT, t = bt - b * TT;
    int n0 = blockIdx.x * ONODES;
    int tid = threadIdx.y * 64 + threadIdx.x;

    {
        int nl   = tid >> 1;
        int part = tid & 1;
        int n = n0 + nl;
        if (n < NNODE) {
            const uint4* ar =
                reinterpret_cast<const uint4*>(g_agg + (size_t)n * FF + (size_t)bt * CC);
            #pragma unroll
            for (int q = 0; q < 2; q++) {
                uint4 v = ar[part * 2 + q];
                int c0 = part * 16 + q * 8;
                const unsigned* u = &v.x;
                #pragma unroll
                for (int j = 0; j < 4; j++) {
                    float2 f = __half22float2(*reinterpret_cast<const __half2*>(&u[j]));
                    s[c0 + 2*j    ][nl] = f.x;
                    s[c0 + 2*j + 1][nl] = f.y;
                }
            }
        }
    }
    __syncthreads();

    int n4 = threadIdx.x * 4;
    int n = n0 + n4;
    if (n < NNODE) {
        #pragma unroll
        for (int k = 0; k < 4; k++) {
            int c = threadIdx.y + k * 8;
            float bc = bias[c];
            size_t idx = (((size_t)b * CC + c) * TT + t) * NNODE + n;
            float4 xv = __ldcs(reinterpret_cast<const float4*>(x + idx));
            float4 av = *reinterpret_cast<const float4*>(&s[c][n4]);
            float4 r;
            r.x = fmaxf(xv.x + bc + av.x, 0.f);
            r.y = fmaxf(xv.y + bc + av.y, 0.f);
            r.z = fmaxf(xv.z + bc + av.z, 0.f);
            r.w = fmaxf(xv.w + bc + av.w, 0.f);
            __stcs(reinterpret_cast<float4*>(out + idx), r);
        }
    }
}

// ---------------------------------------------------------------------------
// Launch: 3 kernels
// ---------------------------------------------------------------------------
extern "C" void kernel_launch(void* const* d_in, const int* in_sizes, int n_in,
                              void* d_out, int out_size) {
    const float* x    = (const float*)d_in[0];  // [B, C, T, N]
    const float* W    = (const float*)d_in[1];  // [C, C]
    const float* bias = (const float*)d_in[2];  // [C]
    const int*   src  = (const int*)d_in[3];    // [E]
    const int*   dst  = (const int*)d_in[4];    // [E]
    float*       out  = (float*)d_out;          // [B, C, T, N]

    k_prep_y<<<PREPB + YBLOCKS, 256>>>(x, W, src, dst);
    k_agg<<<AGGBLOCKS, 384>>>();
    k_out<<<dim3((NNODE + ONODES - 1) / ONODES, BT), dim3(64, 8)>>>(x, bias, out);
}

// round 15
// speedup vs baseline: 1.8074x; 1.0483x over previous
#include <cuda_runtime.h>
#include <cuda_fp16.h>
#include <cuda_bf16.h>

// Problem constants
#define BB 8
#define CC 32
#define TT 12
#define NNODE 5000
#define EDGES 80000
#define FF (BB*TT*CC)       // 3072 features per node
#define BT (BB*TT)          // 96
#define EPAD (EDGES + NNODE*3 + 8)  // padded CSR capacity (pad-to-4)

#define NTILES 157                  // ceil(5000/32)
#define YBLOCKS (NTILES * (BT/8))   // 157*12 = 1884 y-blocks
#define PREPB 120                   // resident prep blocks (phase-barriered)
#define AGGBLOCKS 592               // persistent k_agg blocks (~4/SM)

// ---------------------------------------------------------------------------
// Scratch (static __device__ arrays — no allocations allowed).
// Counters zeroed after last use each call; first call relies on zero-init.
// g_y row NNODE (dummy) is NEVER written -> stays zero from static init.
// ---------------------------------------------------------------------------
__device__ __align__(16) __half g_y  [(size_t)(NNODE + 1) * FF]; // +1 dummy zero row
__device__ __align__(16) __half g_agg[(size_t)NNODE * FF];
__device__ int    g_deg_in [NNODE];
__device__ int    g_deg_out[NNODE];
__device__ int    g_cursor [NNODE];
__device__ int    g_ptr    [NNODE + 1];          // padded CSR row ptr by dst
__device__ __align__(16) unsigned g_csr[EPAD];   // (fp16 ns_src << 16) | src
__device__ float  g_norm_src[NNODE];
__device__ float  g_norm_dst[NNODE];
__device__ int    g_work;                        // k_agg work-stealing counter
__device__ int    g_bar_cnt;                     // prep phase barrier counter

// Packed 2xfp32 FMA (Blackwell FFMA2 — only reachable via PTX f32x2)
__device__ __forceinline__ unsigned long long ffma2(
    unsigned long long a, unsigned long long b, unsigned long long c) {
    unsigned long long d;
    asm("fma.rn.f32x2 %0, %1, %2, %3;" : "=l"(d) : "l"(a), "l"(b), "l"(c));
    return d;
}

// Phase barrier for the PREPB resident blocks. Not a deadlock risk: prep
// blocks are blockIdx 0..119 (all wave-1 resident), y-blocks never wait.
__device__ __forceinline__ void prep_bar(int target) {
    __syncthreads();
    if (threadIdx.x == 0) {
        __threadfence();
        atomicAdd(&g_bar_cnt, 1);
        while (atomicAdd(&g_bar_cnt, 0) < target) __nanosleep(64);
    }
    __syncthreads();
}

// build half2(ns, ns) from packed CSR word (ns fp16 bits in [31:16])
__device__ __forceinline__ __half2 mkns2(unsigned u) {
    unsigned r = (u & 0xFFFF0000u) | (u >> 16);
    return *reinterpret_cast<__half2*>(&r);
}

// ---------------------------------------------------------------------------
// K1: ONE kernel = prep chain (120 barriered blocks) + y'-GEMM (1884 blocks).
// y branch restructured for L1 pressure: thread = (16 c' columns) x (2 bt),
// so each LDS.128 of W feeds 4 FFMA2 (was 2) -> kernel LDS wavefronts halved.
// y' = xW (UNNORMALIZED; norm_src applied in k_agg via packed fp16 ns).
// ---------------------------------------------------------------------------
__global__ __launch_bounds__(256, 4)
void k_prep_y(const float* __restrict__ x, const float* __restrict__ W,
              const int* __restrict__ src, const int* __restrict__ dst) {
    if (blockIdx.x < PREPB) {
        // ================= prep branch =================
        const int tid  = threadIdx.x;
        const int gtid = blockIdx.x * 256 + tid;

        // phase A: degree histograms (distributed global atomics)
        for (int e = gtid; e < EDGES; e += PREPB * 256) {
            atomicAdd(&g_deg_out[src[e]], 1);
            atomicAdd(&g_deg_in [dst[e]], 1);
        }
        prep_bar(PREPB);

        // phase B: block 0 only — norms + padded exclusive scan
        if (blockIdx.x == 0) {
            __shared__ int s_wsum[8];
            const int lane = tid & 31;
            const int warp = tid >> 5;

            if (tid == 0) g_work = 0;

            for (int i = tid; i < NNODE; i += 256) {
                g_norm_src[i] = rsqrtf((float)max(g_deg_out[i], 1));
                g_norm_dst[i] = rsqrtf((float)max(g_deg_in [i], 1));
            }

            // scan of pad-4 degrees: 20 nodes/thread (256*20 = 5120)
            const int base = tid * 20;
            int pd[20];
            int tsum = 0;
            #pragma unroll
            for (int k = 0; k < 20; k++) {
                int dg = (base + k < NNODE) ? g_deg_in[base + k] : 0;
                pd[k] = (dg + 3) & ~3;
                tsum += pd[k];
            }
            int incl = tsum;
            #pragma unroll
            for (int off = 1; off < 32; off <<= 1) {
                int t = __shfl_up_sync(0xffffffffu, incl, off);
                if (lane >= off) incl += t;
            }
            if (lane == 31) s_wsum[warp] = incl;
            __syncthreads();
            if (tid == 0) {
                int r = 0;
                #pragma unroll
                for (int w = 0; w < 8; w++) { int t = s_wsum[w]; s_wsum[w] = r; r += t; }
            }
            __syncthreads();

            int run = s_wsum[warp] + incl - tsum;
            #pragma unroll
            for (int k = 0; k < 20; k++) {
                int idx = base + k;
                if (idx < NNODE) { g_ptr[idx] = run; run += pd[k]; }
            }
            if (tid == (NNODE + 19) / 20 - 1) g_ptr[NNODE] = run;
        }
        prep_bar(2 * PREPB);

        // phase C: scatter (pack fp16 norm_src into bits [31:16]) + pad fill
        for (int e = gtid; e < EDGES; e += PREPB * 256) {
            int s = src[e], d = dst[e];
            int pos = __ldcg(&g_ptr[d]) + atomicAdd(&g_cursor[d], 1);
            unsigned nsb = (unsigned)__half_as_ushort(
                               __float2half_rn(__ldcg(&g_norm_src[s])));
            g_csr[pos] = (unsigned)s | (nsb << 16);
        }
        for (int i = gtid; i < NNODE; i += PREPB * 256) {
            int p  = __ldcg(&g_ptr[i]);
            int dg = __ldcg(&g_deg_in[i]);
            int pad = (dg + 3) & ~3;
            for (int j = dg; j < pad; j++) g_csr[p + j] = NNODE;  // ns=0, zero row
        }
        return;
    }

    // ================= y' branch (no prep dependency) =================
    __shared__ __align__(16) float2 Ws2[CC * CC / 2];
    int tid = threadIdx.x;
    int tx = tid & 31, ty = tid >> 5;
    for (int i = tid; i < CC * CC / 2; i += 256)
        Ws2[i] = reinterpret_cast<const float2*>(W)[i];
    __syncthreads();

    int yb  = blockIdx.x - PREPB;
    int nt  = yb % NTILES;
    int btt = yb / NTILES;
    int n   = nt * 32 + tx;
    if (n >= NNODE) return;

    const int h   = ty & 1;          // c' half: columns [h*16, h*16+16)
    const int bp  = ty >> 1;         // bt-pair slot 0..3
    const int bt0 = btt * 8 + bp * 2;
    const int bt1 = bt0 + 1;
    const int b0 = bt0 / TT, t0 = bt0 - b0 * TT;
    const int b1 = bt1 / TT, t1 = bt1 - b1 * TT;

    const size_t cstride = (size_t)TT * NNODE;
    const float* xpA = x + ((size_t)b0 * CC * TT) * NNODE + (size_t)t0 * NNODE + n;
    const float* xpB = x + ((size_t)b1 * CC * TT) * NNODE + (size_t)t1 * NNODE + n;

    unsigned long long accA[8], accB[8];
    #pragma unroll
    for (int j = 0; j < 8; j++) { accA[j] = 0ull; accB[j] = 0ull; }

    // software-pipelined c-loop: 8 chunks of 4, double-buffered x loads
    float xaA[4], xaB[4], xnA[4], xnB[4];
    #pragma unroll
    for (int k = 0; k < 4; k++) {
        xaA[k] = __ldcs(xpA + (size_t)k * cstride);
        xaB[k] = __ldcs(xpB + (size_t)k * cstride);
        xnA[k] = 0.0f; xnB[k] = 0.0f;
    }

    #pragma unroll
    for (int ch = 0; ch < 8; ch++) {
        if (ch < 7) {
            #pragma unroll
            for (int k = 0; k < 4; k++) {
                xnA[k] = __ldcs(xpA + (size_t)(ch * 4 + 4 + k) * cstride);
                xnB[k] = __ldcs(xpB + (size_t)(ch * 4 + 4 + k) * cstride);
            }
        }
        #pragma unroll
        for (int kc = 0; kc < 4; kc++) {
            int c = ch * 4 + kc;
            unsigned long long xvA, xvB;
            asm("mov.b64 %0, {%1, %1};" : "=l"(xvA) : "f"(xaA[kc]));
            asm("mov.b64 %0, {%1, %1};" : "=l"(xvB) : "f"(xaB[kc]));
            // 16 c' floats for this (c, h): 4 LDS.128 = 8 f32x2 operands
            const ulonglong2* wr =
                reinterpret_cast<const ulonglong2*>(Ws2 + c * (CC / 2) + h * 8);
            #pragma unroll
            for (int q = 0; q < 4; q++) {
                ulonglong2 w = wr[q];
                accA[2*q]     = ffma2(xvA, w.x, accA[2*q]);
                accB[2*q]     = ffma2(xvB, w.x, accB[2*q]);
                accA[2*q + 1] = ffma2(xvA, w.y, accA[2*q + 1]);
                accB[2*q + 1] = ffma2(xvB, w.y, accB[2*q + 1]);
            }
        }
        #pragma unroll
        for (int k = 0; k < 4; k++) { xaA[k] = xnA[k]; xaB[k] = xnB[k]; }
    }

    // pack fp16 (unnormalized) and store: 16 c' x 2 bt = 2x2 uint4
    unsigned oA[8], oB[8];
    #pragma unroll
    for (int j = 0; j < 8; j++) {
        float lo, hi;
        asm("mov.b64 {%0, %1}, %2;" : "=f"(lo), "=f"(hi) : "l"(accA[j]));
        __half2 hh = __floats2half2_rn(lo, hi);
        oA[j] = *reinterpret_cast<unsigned*>(&hh);
        asm("mov.b64 {%0, %1}, %2;" : "=f"(lo), "=f"(hi) : "l"(accB[j]));
        hh = __floats2half2_rn(lo, hi);
        oB[j] = *reinterpret_cast<unsigned*>(&hh);
    }
    uint4* ypA = reinterpret_cast<uint4*>(
        g_y + (size_t)n * FF + (size_t)bt0 * CC + h * 16);
    uint4* ypB = reinterpret_cast<uint4*>(
        g_y + (size_t)n * FF + (size_t)bt1 * CC + h * 16);
    ypA[0] = make_uint4(oA[0], oA[1], oA[2], oA[3]);
    ypA[1] = make_uint4(oA[4], oA[5], oA[6], oA[7]);
    ypB[0] = make_uint4(oB[0], oB[1], oB[2], oB[3]);
    ypB[1] = make_uint4(oB[4], oB[5], oB[6], oB[7]);
}

// ---------------------------------------------------------------------------
// K2: persistent work-stealing aggregation.
// agg[d] = norm_dst[d] * sum_e ns_src(e) * y'[src(e)]
// 8-edge main loop (8-deep MLP), two independent 4-edge HFMA2 chains with
// per-edge ns from the packed CSR word. fp32 upconvert per chain; 4-edge
// tail. Zeroes counters + barrier counter for next replay.
// ---------------------------------------------------------------------------
__global__ __launch_bounds__(384)
void k_agg() {
    __shared__ int s_d;
    int tid = threadIdx.x;
    if (blockIdx.x == 0 && tid == 0) g_bar_cnt = 0;   // reset prep barrier

    while (true) {
        if (tid == 0) s_d = atomicAdd(&g_work, 1);
        __syncthreads();
        int d = s_d;
        __syncthreads();
        if (d >= NNODE) return;

        if (tid == 0) {
            g_deg_in[d] = 0;
            g_deg_out[d] = 0;
            g_cursor[d] = 0;
        }

        int beg = g_ptr[d], end = g_ptr[d + 1];   // multiple of 4, 16B-aligned

        float2 acc[4];
        #pragma unroll
        for (int j = 0; j < 4; j++) acc[j] = make_float2(0.f, 0.f);

        int g0 = beg;
        for (; g0 + 8 <= end; g0 += 8) {
            uint4 i0 = *reinterpret_cast<const uint4*>(&g_csr[g0]);
            uint4 i1 = *reinterpret_cast<const uint4*>(&g_csr[g0 + 4]);
            unsigned u[8] = { i0.x, i0.y, i0.z, i0.w, i1.x, i1.y, i1.z, i1.w };
            uint4 v[8];
            #pragma unroll
            for (int k = 0; k < 8; k++)
                v[k] = reinterpret_cast<const uint4*>(
                           g_y + (size_t)(u[k] & 0xFFFFu) * FF)[tid];
            __half2 ha[4], hb[4];
            #pragma unroll
            for (int j = 0; j < 4; j++) {
                ha[j] = __floats2half2_rn(0.f, 0.f);
                hb[j] = __floats2half2_rn(0.f, 0.f);
            }
            #pragma unroll
            for (int k = 0; k < 4; k++) {
                __half2 nA = mkns2(u[k]);
                __half2 nB = mkns2(u[k + 4]);
                #pragma unroll
                for (int j = 0; j < 4; j++) {
                    ha[j] = __hfma2(*reinterpret_cast<const __half2*>(&(&v[k].x)[j]),
                                    nA, ha[j]);
                    hb[j] = __hfma2(*reinterpret_cast<const __half2*>(&(&v[k+4].x)[j]),
                                    nB, hb[j]);
                }
            }
            #pragma unroll
            for (int j = 0; j < 4; j++) {
                float2 fa = __half22float2(ha[j]);
                float2 fb = __half22float2(hb[j]);
                acc[j].x += fa.x + fb.x;
                acc[j].y += fa.y + fb.y;
            }
        }
        if (g0 < end) {            // tail: one group of 4
            uint4 i0 = *reinterpret_cast<const uint4*>(&g_csr[g0]);
            unsigned u[4] = { i0.x, i0.y, i0.z, i0.w };
            uint4 v[4];
            #pragma unroll
            for (int k = 0; k < 4; k++)
                v[k] = reinterpret_cast<const uint4*>(
                           g_y + (size_t)(u[k] & 0xFFFFu) * FF)[tid];
            #pragma unroll
            for (int j = 0; j < 4; j++) {
                __half2 h = __floats2half2_rn(0.f, 0.f);
                #pragma unroll
                for (int k = 0; k < 4; k++)
                    h = __hfma2(*reinterpret_cast<const __half2*>(&(&v[k].x)[j]),
                                mkns2(u[k]), h);
                float2 f = __half22float2(h);
                acc[j].x += f.x; acc[j].y += f.y;
            }
        }

        float nd = g_norm_dst[d];
        __half2 o[4];
        #pragma unroll
        for (int j = 0; j < 4; j++)
            o[j] = __floats2half2_rn(acc[j].x * nd, acc[j].y * nd);
        uint4 pack;
        pack.x = *reinterpret_cast<unsigned*>(&o[0]);
        pack.y = *reinterpret_cast<unsigned*>(&o[1]);
        pack.z = *reinterpret_cast<unsigned*>(&o[2]);
        pack.w = *reinterpret_cast<unsigned*>(&o[3]);
        reinterpret_cast<uint4*>(g_agg + (size_t)d * FF)[tid] = pack;
    }
}

// ---------------------------------------------------------------------------
// K3: out[b,c,t,n] = relu(x[b,c,t,n] + bias[c] + agg[n][b][t][c])
// ---------------------------------------------------------------------------
#define ONODES 256
__global__ __launch_bounds__(512, 3)
void k_out(const float* __restrict__ x, const float* __restrict__ bias,
           float* __restrict__ out) {
    __shared__ float s[CC][ONODES + 4];
    int bt = blockIdx.y;
    int b = bt / TT, t = bt - b * TT;
    int n0 = blockIdx.x * ONODES;
    int tid = threadIdx.y * 64 + threadIdx.x;

    {
        int nl   = tid >> 1;
        int part = tid & 1;
        int n = n0 + nl;
        if (n < NNODE) {
            const uint4* ar =
                reinterpret_cast<const uint4*>(g_agg + (size_t)n * FF + (size_t)bt * CC);
            #pragma unroll
            for (int q = 0; q < 2; q++) {
                uint4 v = ar[part * 2 + q];
                int c0 = part * 16 + q * 8;
                const unsigned* u = &v.x;
                #pragma unroll
                for (int j = 0; j < 4; j++) {
                    float2 f = __half22float2(*reinterpret_cast<const __half2*>(&u[j]));
                    s[c0 + 2*j    ][nl] = f.x;
                    s[c0 + 2*j + 1][nl] = f.y;
                }
            }
        }
    }
    __syncthreads();

    int n4 = threadIdx.x * 4;
    int n = n0 + n4;
    if (n < NNODE) {
        #pragma unroll
        for (int k = 0; k < 4; k++) {
            int c = threadIdx.y + k * 8;
            float bc = bias[c];
            size_t idx = (((size_t)b * CC + c) * TT + t) * NNODE + n;
            float4 xv = __ldcs(reinterpret_cast<const float4*>(x + idx));
            float4 av = *reinterpret_cast<const float4*>(&s[c][n4]);
            float4 r;
            r.x = fmaxf(xv.x + bc + av.x, 0.f);
            r.y = fmaxf(xv.y + bc + av.y, 0.f);
            r.z = fmaxf(xv.z + bc + av.z, 0.f);
            r.w = fmaxf(xv.w + bc + av.w, 0.f);
            __stcs(reinterpret_cast<float4*>(out + idx), r);
        }
    }
}

// ---------------------------------------------------------------------------
// Launch: 3 kernels
// ---------------------------------------------------------------------------
extern "C" void kernel_launch(void* const* d_in, const int* in_sizes, int n_in,
                              void* d_out, int out_size) {
    const float* x    = (const float*)d_in[0];  // [B, C, T, N]
    const float* W    = (const float*)d_in[1];  // [C, C]
    const float* bias = (const float*)d_in[2];  // [C]
    const int*   src  = (const int*)d_in[3];    // [E]
    const int*   dst  = (const int*)d_in[4];    // [E]
    float*       out  = (float*)d_out;          // [B, C, T, N]

    k_prep_y<<<PREPB + YBLOCKS, 256>>>(x, W, src, dst);
    k_agg<<<AGGBLOCKS, 384>>>();
    k_out<<<dim3((NNODE + ONODES - 1) / ONODES, BT), dim3(64, 8)>>>(x, bias, out);
}